// round 6
// baseline (speedup 1.0000x reference)
#include <cuda_runtime.h>

#define Bb  256
#define Tt  256
#define Cc  384
#define Hh  6
#define HSs 64
#define Pp  307
#define PPAD 384
#define BT  (Bb*Tt)            // 65536 tokens
#define C3  (3*Cc)             // 1152
#define NS_ITERS 36
#define NS_CTAS 144
#define MSZ (Cc*Cc)            // 147456

// ---------------- scratch (device globals; no allocation at runtime) ----------------
__device__ float g_h1  [(size_t)BT*Cc];
__device__ float g_qkv [(size_t)BT*C3];
__device__ float g_attn[(size_t)BT*Cc];
__device__ float g_h2  [(size_t)BT*Cc];
__device__ float g_h3  [(size_t)BT*Cc];
__device__ float g_h4  [(size_t)BT*Cc];
__device__ float g_ff  [(size_t)BT*PPAD];
__device__ float g_h6  [(size_t)BT*Cc];
__device__ float g_X0  [2*MSZ];
__device__ float g_X1  [2*MSZ];
__device__ float g_Tm  [2*MSZ];
__device__ float g_Wqkv[Cc*C3];
__device__ float g_part[NS_CTAS];
__device__ unsigned g_barCnt;
__device__ unsigned g_barGen;

// ================= software grid barrier =================
__device__ __forceinline__ void gridbar() {
    __syncthreads();
    if (threadIdx.x == 0) {
        __threadfence();
        volatile unsigned* vg = &g_barGen;
        unsigned gen = *vg;
        unsigned old = atomicAdd(&g_barCnt, 1u);
        if (old == NS_CTAS - 1) {
            g_barCnt = 0;
            __threadfence();
            *vg = gen + 1;
        } else {
            while (*vg == gen) { }
        }
        __threadfence();
    }
    __syncthreads();
}

// ================= persistent Newton-Schulz polar orthogonalization =================
__global__ __launch_bounds__(256)
void ns_k(const float* __restrict__ Win, const float* __restrict__ Wout)
{
    int bx = blockIdx.x, tid = threadIdx.x;
    int lane = tid & 31, wid = tid >> 5;
    int b  = bx / 72;
    int t  = bx % 72;
    int tm = t / 6;
    int tn = t % 6;
    int ty = tid >> 4;
    int tx = tid & 15;

    __shared__ float As[16][36];
    __shared__ float Bs[16][72];
    __shared__ float red[8];
    __shared__ float ssc[2];

    const float* W = b ? Wout : Win;

    {
        long off = (long)t * 2048;
        float ss = 0.f;
        #pragma unroll
        for (int i = 0; i < 8; i++) { float w = W[off + tid + i * 256]; ss += w * w; }
        #pragma unroll
        for (int o = 16; o > 0; o >>= 1) ss += __shfl_xor_sync(0xffffffffu, ss, o);
        if (lane == 0) red[wid] = ss;
        __syncthreads();
        if (tid == 0) {
            float s = 0.f;
            #pragma unroll
            for (int i = 0; i < 8; i++) s += red[i];
            __stcg(&g_part[bx], s);
        }
    }
    gridbar();

    if (tid < 2) {
        float s = 0.f;
        for (int i = 0; i < 72; i++) s += __ldcg(&g_part[tid * 72 + i]);
        ssc[tid] = rsqrtf(s);
    }
    __syncthreads();
    float rs = ssc[b];

    {
        long off = (long)t * 2048;
        #pragma unroll
        for (int i = 0; i < 8; i++)
            __stcg(&g_X0[(long)b * MSZ + off + tid + i * 256], W[off + tid + i * 256] * rs);
    }
    gridbar();

    float* Xc = g_X0;
    float* Xn = g_X1;

    for (int it = 0; it < NS_ITERS; it++) {
        const float* X = Xc + (long)b * MSZ;
        float* T       = g_Tm + (long)b * MSZ;

        float acc[2][4] = {};
        for (int k0 = 0; k0 < Cc; k0 += 16) {
            if (tid < 128) {
                int r = tid >> 2, q = tid & 3;
                float4 v = __ldcg((const float4*)(X + (long)(tm * 32 + r) * Cc + k0 + q * 4));
                As[q*4+0][r] = v.x; As[q*4+1][r] = v.y; As[q*4+2][r] = v.z; As[q*4+3][r] = v.w;
            }
            {
                int r = tid >> 2, q = tid & 3;
                float4 v = __ldcg((const float4*)(X + (long)(tn * 64 + r) * Cc + k0 + q * 4));
                Bs[q*4+0][r] = v.x; Bs[q*4+1][r] = v.y; Bs[q*4+2][r] = v.z; Bs[q*4+3][r] = v.w;
            }
            __syncthreads();
            #pragma unroll
            for (int k = 0; k < 16; k++) {
                float a0 = As[k][ty*2], a1 = As[k][ty*2+1];
                float b0 = Bs[k][tx*4], b1 = Bs[k][tx*4+1], b2 = Bs[k][tx*4+2], b3 = Bs[k][tx*4+3];
                acc[0][0] = fmaf(a0,b0,acc[0][0]); acc[0][1] = fmaf(a0,b1,acc[0][1]);
                acc[0][2] = fmaf(a0,b2,acc[0][2]); acc[0][3] = fmaf(a0,b3,acc[0][3]);
                acc[1][0] = fmaf(a1,b0,acc[1][0]); acc[1][1] = fmaf(a1,b1,acc[1][1]);
                acc[1][2] = fmaf(a1,b2,acc[1][2]); acc[1][3] = fmaf(a1,b3,acc[1][3]);
            }
            __syncthreads();
        }
        #pragma unroll
        for (int i = 0; i < 2; i++)
            #pragma unroll
            for (int j = 0; j < 4; j++)
                __stcg(&T[(long)(tm * 32 + ty * 2 + i) * Cc + tn * 64 + tx * 4 + j], acc[i][j]);
        gridbar();

        float ac2[2][4] = {};
        for (int k0 = 0; k0 < Cc; k0 += 16) {
            if (tid < 128) {
                int r = tid >> 2, q = tid & 3;
                float4 v = __ldcg((const float4*)(T + (long)(tm * 32 + r) * Cc + k0 + q * 4));
                As[q*4+0][r] = v.x; As[q*4+1][r] = v.y; As[q*4+2][r] = v.z; As[q*4+3][r] = v.w;
            }
            {
                int kk = tid >> 4, n4 = tid & 15;
                float4 v = __ldcg((const float4*)(X + (long)(k0 + kk) * Cc + tn * 64 + n4 * 4));
                Bs[kk][n4*4+0] = v.x; Bs[kk][n4*4+1] = v.y; Bs[kk][n4*4+2] = v.z; Bs[kk][n4*4+3] = v.w;
            }
            __syncthreads();
            #pragma unroll
            for (int k = 0; k < 16; k++) {
                float a0 = As[k][ty*2], a1 = As[k][ty*2+1];
                float b0 = Bs[k][tx*4], b1 = Bs[k][tx*4+1], b2 = Bs[k][tx*4+2], b3 = Bs[k][tx*4+3];
                ac2[0][0] = fmaf(a0,b0,ac2[0][0]); ac2[0][1] = fmaf(a0,b1,ac2[0][1]);
                ac2[0][2] = fmaf(a0,b2,ac2[0][2]); ac2[0][3] = fmaf(a0,b3,ac2[0][3]);
                ac2[1][0] = fmaf(a1,b0,ac2[1][0]); ac2[1][1] = fmaf(a1,b1,ac2[1][1]);
                ac2[1][2] = fmaf(a1,b2,ac2[1][2]); ac2[1][3] = fmaf(a1,b3,ac2[1][3]);
            }
            __syncthreads();
        }
        {
            float* Xnb = Xn + (long)b * MSZ;
            #pragma unroll
            for (int i = 0; i < 2; i++)
                #pragma unroll
                for (int j = 0; j < 4; j++) {
                    long idx = (long)(tm * 32 + ty * 2 + i) * Cc + tn * 64 + tx * 4 + j;
                    float xv = __ldcg(&X[idx]);
                    __stcg(&Xnb[idx], 1.5f * xv - 0.5f * ac2[i][j]);
                }
        }
        gridbar();
        float* tp = Xc; Xc = Xn; Xn = tp;
    }
}

// ================= tf32 mma primitives =================
__device__ __forceinline__ unsigned f2tf32(float f) {
    unsigned u; asm("cvt.rna.tf32.f32 %0, %1;" : "=r"(u) : "f"(f)); return u;
}
__device__ __forceinline__ void mma8(float* c, unsigned a0, unsigned a1, unsigned a2, unsigned a3,
                                     unsigned b0, unsigned b1) {
    asm volatile(
        "mma.sync.aligned.m16n8k8.row.col.f32.tf32.tf32.f32 "
        "{%0,%1,%2,%3}, {%4,%5,%6,%7}, {%8,%9}, {%0,%1,%2,%3};"
        : "+f"(c[0]), "+f"(c[1]), "+f"(c[2]), "+f"(c[3])
        : "r"(a0), "r"(a1), "r"(a2), "r"(a3), "r"(b0), "r"(b1));
}

// ================= tf32 tensor-core GEMM: BM=256 BN=128 BK=16, warp 64x64 =================
#define GEMM_SMEM ((2*256*20 + 2*16*136) * 4)
template<bool RELU, bool BIAS, bool RES>
__global__ __launch_bounds__(256, 1)
void gemm_tc(const float* __restrict__ A, const float* __restrict__ B,
             const float* __restrict__ bias, const float* __restrict__ Res,
             float* __restrict__ C,
             int Nstore, int K, int lda, int ldb, int Nreal, int Kb)
{
    extern __shared__ unsigned smg[];
    unsigned* Asb = smg;              // [2][256][20]
    unsigned* Bsb = smg + 2*256*20;   // [2][16][136]
    #define ASI(bf,r,q) Asb[(bf)*5120 + (r)*20 + (q)]
    #define BSI(bf,k,n) Bsb[(bf)*2176 + (k)*136 + (n)]

    int tid = threadIdx.x;
    int lane = tid & 31, w = tid >> 5;
    int gr = lane >> 2, tg = lane & 3;
    int wm = w & 3, wn = w >> 2;          // warp tile rows wm*64, cols wn*64
    long m0 = (long)blockIdx.y * 256;
    int n0 = blockIdx.x * 128;

    int ar = tid >> 2, aq = tid & 3;      // A loader: rows ar + h*64
    int bk = tid >> 4, bn = tid & 15;     // B loader

    float acc[4][8][4];
    #pragma unroll
    for (int i = 0; i < 4; i++)
        #pragma unroll
        for (int j = 0; j < 8; j++)
            #pragma unroll
            for (int e = 0; e < 4; e++) acc[i][j][e] = 0.f;

    int nk = K / 16;

    // prologue: tile 0 -> buf 0
    {
        #pragma unroll
        for (int h = 0; h < 4; h++) {
            int row = ar + h * 64;
            float4 v = *(const float4*)(A + (m0 + row) * lda + aq * 4);
            uint4 u = { f2tf32(v.x), f2tf32(v.y), f2tf32(v.z), f2tf32(v.w) };
            *(uint4*)&ASI(0, row, aq * 4) = u;
        }
        #pragma unroll
        for (int j = 0; j < 8; j++) {
            int n = bn + j * 16;
            int gn = n0 + n;
            float v = 0.f;
            if (bk < Kb && gn < Nreal) v = B[(long)bk * ldb + gn];
            BSI(0, bk, n) = f2tf32(v);
        }
    }
    __syncthreads();

    for (int kt = 0; kt < nk; kt++) {
        int cur = kt & 1, nxt = cur ^ 1;
        bool more = (kt + 1 < nk);
        float4 ra[4];
        float rb[8];
        if (more) {
            int k0 = (kt + 1) * 16;
            #pragma unroll
            for (int h = 0; h < 4; h++) {
                int row = ar + h * 64;
                ra[h] = *(const float4*)(A + (m0 + row) * lda + k0 + aq * 4);
            }
            #pragma unroll
            for (int j = 0; j < 8; j++) {
                int n = bn + j * 16;
                int gk = k0 + bk, gn = n0 + n;
                rb[j] = (gk < Kb && gn < Nreal) ? B[(long)gk * ldb + gn] : 0.f;
            }
        }

        #pragma unroll
        for (int ks = 0; ks < 2; ks++) {
            int kb = ks * 8;
            unsigned bf[8][2];
            #pragma unroll
            for (int nt = 0; nt < 8; nt++) {
                int ncol = wn * 64 + nt * 8;
                bf[nt][0] = BSI(cur, kb + tg    , ncol + gr);
                bf[nt][1] = BSI(cur, kb + tg + 4, ncol + gr);
            }
            #pragma unroll
            for (int mt = 0; mt < 4; mt++) {
                int mrow = wm * 64 + mt * 16;
                unsigned a0 = ASI(cur, mrow + gr    , kb + tg    );
                unsigned a1 = ASI(cur, mrow + gr + 8, kb + tg    );
                unsigned a2 = ASI(cur, mrow + gr    , kb + tg + 4);
                unsigned a3 = ASI(cur, mrow + gr + 8, kb + tg + 4);
                #pragma unroll
                for (int nt = 0; nt < 8; nt++)
                    mma8(acc[mt][nt], a0, a1, a2, a3, bf[nt][0], bf[nt][1]);
            }
        }

        if (more) {
            #pragma unroll
            for (int h = 0; h < 4; h++) {
                int row = ar + h * 64;
                uint4 u = { f2tf32(ra[h].x), f2tf32(ra[h].y), f2tf32(ra[h].z), f2tf32(ra[h].w) };
                *(uint4*)&ASI(nxt, row, aq * 4) = u;
            }
            #pragma unroll
            for (int j = 0; j < 8; j++) BSI(nxt, bk, bn + j * 16) = f2tf32(rb[j]);
        }
        __syncthreads();
    }

    // epilogue
    #pragma unroll
    for (int mt = 0; mt < 4; mt++) {
        #pragma unroll
        for (int nt = 0; nt < 8; nt++) {
            int r0 = wm * 64 + mt * 16 + gr;
            int cb = n0 + wn * 64 + nt * 8 + 2 * tg;
            if (cb >= Nstore) continue;
            #pragma unroll
            for (int half = 0; half < 2; half++) {
                long gm = m0 + r0 + half * 8;
                float v0 = acc[mt][nt][half * 2 + 0];
                float v1 = acc[mt][nt][half * 2 + 1];
                if (BIAS) {
                    v0 += (cb     < Nreal) ? bias[cb]     : 0.f;
                    v1 += (cb + 1 < Nreal) ? bias[cb + 1] : 0.f;
                }
                if (RES) {
                    float2 rr = *(const float2*)(Res + gm * Nstore + cb);
                    v0 += rr.x; v1 += rr.y;
                }
                if (RELU) { v0 = fmaxf(v0, 0.f); v1 = fmaxf(v1, 0.f); }
                *(float2*)(C + gm * Nstore + cb) = make_float2(v0, v1);
            }
        }
    }
    #undef ASI
    #undef BSI
}

// ---------------- rmsnorm ----------------
__global__ __launch_bounds__(256)
void rmsnorm_k(const float* __restrict__ x, const float* __restrict__ scale,
               float* __restrict__ out)
{
    int warp = threadIdx.x >> 5, lane = threadIdx.x & 31;
    long t = (long)blockIdx.x * 8 + warp;
    const float* xr = x + t * Cc;
    float v[12], ss = 0.f;
    #pragma unroll
    for (int i = 0; i < 12; i++) { v[i] = xr[lane + i * 32]; ss += v[i] * v[i]; }
    #pragma unroll
    for (int o = 16; o > 0; o >>= 1) ss += __shfl_xor_sync(0xffffffffu, ss, o);
    float inv = rsqrtf(ss * (1.0f / Cc) + 1e-6f);
    float* orow = out + t * Cc;
    #pragma unroll
    for (int i = 0; i < 12; i++) orow[lane + i * 32] = v[i] * inv * scale[lane + i * 32];
}

// ---------------- pack ----------------
__global__ void pack_k(const float* __restrict__ Wq, const float* __restrict__ Wk,
                       const float* __restrict__ Wv, float* __restrict__ Wqkv)
{
    int i = blockIdx.x * 256 + threadIdx.x;
    if (i >= Hh * Cc * HSs) return;
    int h = i / (Cc * HSs);
    int rem = i % (Cc * HSs);
    int c = rem / HSs, d = rem % HSs;
    long row = (long)c * C3;
    Wqkv[row +           h * HSs + d] = Wq[i];
    Wqkv[row + Cc      + h * HSs + d] = Wk[i];
    Wqkv[row + 2 * Cc  + h * HSs + d] = Wv[i];
}

// ================= tensor-core causal flash attention (tf32) =================
// grid (2, 6, 256), 256 thr = 8 warps. CTA: 128 q rows; warp w owns rows w*16..+16 (all 64 cols).
#define FQ 68
#define FV 72
#define FLASH_SMEM ((128*FQ + 64*FQ + 64*FV + 128*FQ) * 4)
__global__ __launch_bounds__(256, 2)
void flash_tc(const float* __restrict__ qkv, float* __restrict__ attn)
{
    extern __shared__ unsigned sm[];
    unsigned* Qs = sm;                 // [128][68]
    unsigned* Ks = Qs + 128 * FQ;      // [64][68]
    unsigned* Vs = Ks + 64 * FQ;       // [64][72]
    unsigned* Ps = Vs + 64 * FV;       // [128][68]

    int qb = blockIdx.x, h = blockIdx.y, b = blockIdx.z;
    int tid = threadIdx.x;
    int lane = tid & 31, w = tid >> 5;
    int gr = lane >> 2, tg = lane & 3;
    int wr = w * 16;

    long base = (long)b * Tt * C3 + (long)h * HSs;

    // stage Q (scaled) -> Qs
    for (int f = tid; f < 128 * 16; f += 256) {
        int row = f >> 4, d4 = f & 15;
        float4 v = *(const float4*)(qkv + base + (long)(qb * 128 + row) * C3 + d4 * 4);
        uint4 u = { f2tf32(v.x * 0.125f), f2tf32(v.y * 0.125f),
                    f2tf32(v.z * 0.125f), f2tf32(v.w * 0.125f) };
        *(uint4*)&Qs[row * FQ + d4 * 4] = u;
    }

    float oacc[8][4];
    #pragma unroll
    for (int i = 0; i < 8; i++)
        #pragma unroll
        for (int j = 0; j < 4; j++) oacc[i][j] = 0.f;
    float m0 = -1e30f, m1 = -1e30f, l0 = 0.f, l1 = 0.f;

    int r0g = qb * 128 + wr + gr;      // global q row (lower half)
    int r1g = r0g + 8;

    int ktmax = 2 * qb + 1;
    for (int kt = 0; kt <= ktmax; kt++) {
        __syncthreads();               // Qs staged (1st) / prior PV reads done
        for (int f = tid; f < 64 * 16; f += 256) {
            int row = f >> 4, d4 = f & 15;
            long off = base + (long)(kt * 64 + row) * C3 + d4 * 4;
            float4 kv = *(const float4*)(qkv + off + Cc);
            float4 vv = *(const float4*)(qkv + off + 2 * Cc);
            uint4 ku = { f2tf32(kv.x), f2tf32(kv.y), f2tf32(kv.z), f2tf32(kv.w) };
            uint4 vu = { f2tf32(vv.x), f2tf32(vv.y), f2tf32(vv.z), f2tf32(vv.w) };
            *(uint4*)&Ks[row * FQ + d4 * 4] = ku;
            *(uint4*)&Vs[row * FV + d4 * 4] = vu;
        }
        __syncthreads();

        // S = Q @ K^T  (warp: 16 rows x 64 cols)
        float sacc[8][4];
        #pragma unroll
        for (int i = 0; i < 8; i++)
            #pragma unroll
            for (int j = 0; j < 4; j++) sacc[i][j] = 0.f;
        #pragma unroll
        for (int ks = 0; ks < 8; ks++) {
            int kb = ks * 8;
            unsigned a0 = Qs[(wr + gr    ) * FQ + kb + tg    ];
            unsigned a1 = Qs[(wr + gr + 8) * FQ + kb + tg    ];
            unsigned a2 = Qs[(wr + gr    ) * FQ + kb + tg + 4];
            unsigned a3 = Qs[(wr + gr + 8) * FQ + kb + tg + 4];
            #pragma unroll
            for (int nt = 0; nt < 8; nt++) {
                unsigned b0 = Ks[(nt * 8 + gr) * FQ + kb + tg    ];
                unsigned b1 = Ks[(nt * 8 + gr) * FQ + kb + tg + 4];
                mma8(sacc[nt], a0, a1, a2, a3, b0, b1);
            }
        }

        // causal mask (global indices; full tiles unaffected)
        #pragma unroll
        for (int nt = 0; nt < 8; nt++) {
            int c = kt * 64 + nt * 8 + 2 * tg;
            if (c     > r0g) sacc[nt][0] = -1e30f;
            if (c + 1 > r0g) sacc[nt][1] = -1e30f;
            if (c     > r1g) sacc[nt][2] = -1e30f;
            if (c + 1 > r1g) sacc[nt][3] = -1e30f;
        }

        // warp-local online softmax (rows fully owned by warp)
        float mx0 = -1e30f, mx1 = -1e30f;
        #pragma unroll
        for (int nt = 0; nt < 8; nt++) {
            mx0 = fmaxf(mx0, fmaxf(sacc[nt][0], sacc[nt][1]));
            mx1 = fmaxf(mx1, fmaxf(sacc[nt][2], sacc[nt][3]));
        }
        mx0 = fmaxf(mx0, __shfl_xor_sync(0xffffffffu, mx0, 1));
        mx0 = fmaxf(mx0, __shfl_xor_sync(0xffffffffu, mx0, 2));
        mx1 = fmaxf(mx1, __shfl_xor_sync(0xffffffffu, mx1, 1));
        mx1 = fmaxf(mx1, __shfl_xor_sync(0xffffffffu, mx1, 2));
        float mn0 = fmaxf(m0, mx0), mn1 = fmaxf(m1, mx1);
        float corr0 = __expf(m0 - mn0), corr1 = __expf(m1 - mn1);

        float rs0 = 0.f, rs1 = 0.f;
        #pragma unroll
        for (int nt = 0; nt < 8; nt++) {
            sacc[nt][0] = __expf(sacc[nt][0] - mn0);
            sacc[nt][1] = __expf(sacc[nt][1] - mn0);
            sacc[nt][2] = __expf(sacc[nt][2] - mn1);
            sacc[nt][3] = __expf(sacc[nt][3] - mn1);
            rs0 += sacc[nt][0] + sacc[nt][1];
            rs1 += sacc[nt][2] + sacc[nt][3];
        }
        rs0 += __shfl_xor_sync(0xffffffffu, rs0, 1);
        rs0 += __shfl_xor_sync(0xffffffffu, rs0, 2);
        rs1 += __shfl_xor_sync(0xffffffffu, rs1, 1);
        rs1 += __shfl_xor_sync(0xffffffffu, rs1, 2);
        l0 = l0 * corr0 + rs0;
        l1 = l1 * corr1 + rs1;
        m0 = mn0; m1 = mn1;
        #pragma unroll
        for (int nt = 0; nt < 8; nt++) {
            oacc[nt][0] *= corr0; oacc[nt][1] *= corr0;
            oacc[nt][2] *= corr1; oacc[nt][3] *= corr1;
        }

        // store P (warp-private rows of Ps)
        #pragma unroll
        for (int nt = 0; nt < 8; nt++) {
            uint2 u0 = { f2tf32(sacc[nt][0]), f2tf32(sacc[nt][1]) };
            uint2 u1 = { f2tf32(sacc[nt][2]), f2tf32(sacc[nt][3]) };
            *(uint2*)&Ps[(wr + gr    ) * FQ + nt * 8 + 2 * tg] = u0;
            *(uint2*)&Ps[(wr + gr + 8) * FQ + nt * 8 + 2 * tg] = u1;
        }
        __syncwarp();

        // O += P @ V
        #pragma unroll
        for (int ks = 0; ks < 8; ks++) {
            int kb = ks * 8;
            unsigned pa0 = Ps[(wr + gr    ) * FQ + kb + tg    ];
            unsigned pa1 = Ps[(wr + gr + 8) * FQ + kb + tg    ];
            unsigned pa2 = Ps[(wr + gr    ) * FQ + kb + tg + 4];
            unsigned pa3 = Ps[(wr + gr + 8) * FQ + kb + tg + 4];
            #pragma unroll
            for (int nt = 0; nt < 8; nt++) {
                unsigned b0 = Vs[(kb + tg    ) * FV + nt * 8 + gr];
                unsigned b1 = Vs[(kb + tg + 4) * FV + nt * 8 + gr];
                mma8(oacc[nt], pa0, pa1, pa2, pa3, b0, b1);
            }
        }
    }

    float i0 = 1.f / l0, i1 = 1.f / l1;
    long orow0 = ((long)b * Tt + qb * 128 + wr + gr) * Cc + h * HSs;
    long orow1 = orow0 + 8L * Cc;
    #pragma unroll
    for (int nt = 0; nt < 8; nt++) {
        int c = nt * 8 + 2 * tg;
        *(float2*)(attn + orow0 + c) = make_float2(oacc[nt][0] * i0, oacc[nt][1] * i0);
        *(float2*)(attn + orow1 + c) = make_float2(oacc[nt][2] * i1, oacc[nt][3] * i1);
    }
}

// ---------------- host side ----------------
static float* symaddr(const void* sym) {
    void* p = nullptr;
    cudaGetSymbolAddress(&p, sym);
    return (float*)p;
}

extern "C" void kernel_launch(void* const* d_in, const int* in_sizes, int n_in,
                              void* d_out, int out_size)
{
    const float* x      = (const float*)d_in[0];
    const float* Wq     = (const float*)d_in[1];
    const float* Wk     = (const float*)d_in[2];
    const float* Wv     = (const float*)d_in[3];
    const float* Wp     = (const float*)d_in[4];
    const float* bp     = (const float*)d_in[5];
    const float* scale1 = (const float*)d_in[6];
    const float* scale2 = (const float*)d_in[7];
    const float* W1     = (const float*)d_in[8];
    const float* b1     = (const float*)d_in[9];
    const float* W2     = (const float*)d_in[10];
    const float* b2     = (const float*)d_in[11];
    const float* Wo_in  = (const float*)d_in[12];
    const float* Wo_out = (const float*)d_in[13];
    float* out = (float*)d_out;

    float* h1   = symaddr(g_h1);
    float* qkv  = symaddr(g_qkv);
    float* attn = symaddr(g_attn);
    float* h2   = symaddr(g_h2);
    float* h3   = symaddr(g_h3);
    float* h4   = symaddr(g_h4);
    float* ff   = symaddr(g_ff);
    float* h6   = symaddr(g_h6);
    float* X0   = symaddr(g_X0);
    float* Wqkv = symaddr(g_Wqkv);

    cudaFuncSetAttribute(flash_tc, cudaFuncAttributeMaxDynamicSharedMemorySize, FLASH_SMEM);
    cudaFuncSetAttribute(gemm_tc<false,false,false>, cudaFuncAttributeMaxDynamicSharedMemorySize, GEMM_SMEM);
    cudaFuncSetAttribute(gemm_tc<false,true,true>,   cudaFuncAttributeMaxDynamicSharedMemorySize, GEMM_SMEM);
    cudaFuncSetAttribute(gemm_tc<true,true,false>,   cudaFuncAttributeMaxDynamicSharedMemorySize, GEMM_SMEM);
    cudaFuncSetAttribute(gemm_tc<false,true,false>,  cudaFuncAttributeMaxDynamicSharedMemorySize, GEMM_SMEM);
    cudaFuncSetAttribute(gemm_tc<false,false,true>,  cudaFuncAttributeMaxDynamicSharedMemorySize, GEMM_SMEM);

    // ---- orth via persistent Newton-Schulz ----
    ns_k<<<NS_CTAS, 256>>>(Wo_in, Wo_out);
    const float* O_in  = X0;
    const float* O_out = X0 + MSZ;

    // ---- pack + ln1 ----
    pack_k<<<(Hh * Cc * HSs + 255) / 256, 256>>>(Wq, Wk, Wv, Wqkv);
    rmsnorm_k<<<BT / 8, 256>>>(x, scale1, h1);

    // ---- qkv = h1 @ Wqkv ----
    gemm_tc<false, false, false><<<dim3(C3 / 128, BT / 256), 256, GEMM_SMEM>>>(
        h1, Wqkv, nullptr, nullptr, qkv, C3, Cc, Cc, C3, C3, Cc);

    // ---- attention ----
    flash_tc<<<dim3(Tt / 128, Hh, Bb), 256, FLASH_SMEM>>>(qkv, attn);

    // ---- h2 = attn @ Wp + bp + h1 ----
    gemm_tc<false, true, true><<<dim3(Cc / 128, BT / 256), 256, GEMM_SMEM>>>(
        attn, Wp, bp, h1, h2, Cc, Cc, Cc, Cc, Cc, Cc);

    // ---- ln2 ----
    rmsnorm_k<<<BT / 8, 256>>>(h2, scale2, h3);

    // ---- h4 = h3 @ O_in ----
    gemm_tc<false, false, false><<<dim3(Cc / 128, BT / 256), 256, GEMM_SMEM>>>(
        h3, O_in, nullptr, nullptr, h4, Cc, Cc, Cc, Cc, Cc, Cc);

    // ---- ff = relu(h4 @ W1 + b1), padded to 384 cols (pad = 0) ----
    gemm_tc<true, true, false><<<dim3(PPAD / 128, BT / 256), 256, GEMM_SMEM>>>(
        h4, W1, b1, nullptr, ff, PPAD, Cc, Cc, Pp, Pp, Cc);

    // ---- h6 = ff @ W2 + b2  (pad cols of ff are zero; B rows guarded to 307) ----
    gemm_tc<false, true, false><<<dim3(Cc / 128, BT / 256), 256, GEMM_SMEM>>>(
        ff, W2, b2, nullptr, h6, Cc, PPAD, PPAD, Cc, Cc, Pp);

    // ---- out = h6 @ O_out + h6 ----
    gemm_tc<false, false, true><<<dim3(Cc / 128, BT / 256), 256, GEMM_SMEM>>>(
        h6, O_out, nullptr, h6, out, Cc, Cc, Cc, Cc, Cc, Cc);

    (void)in_sizes; (void)n_in; (void)out_size;
}

// round 10
// speedup vs baseline: 1.1139x; 1.1139x over previous
#include <cuda_runtime.h>

#define Bb  256
#define Tt  256
#define Cc  384
#define Hh  6
#define HSs 64
#define Pp  307
#define PPAD 384
#define BT  (Bb*Tt)            // 65536 tokens
#define C3  (3*Cc)             // 1152
#define NS_ITERS 36
#define NS_CTAS 144
#define MSZ (Cc*Cc)            // 147456

// ---------------- scratch (device globals; no allocation at runtime) ----------------
__device__ float g_h1  [(size_t)BT*Cc];
__device__ float g_qkv [(size_t)BT*C3];
__device__ float g_attn[(size_t)BT*Cc];
__device__ float g_h2  [(size_t)BT*Cc];
__device__ float g_h3  [(size_t)BT*Cc];
__device__ float g_h4  [(size_t)BT*Cc];
__device__ float g_ff  [(size_t)BT*PPAD];
__device__ float g_h6  [(size_t)BT*Cc];
__device__ float g_X0  [2*MSZ];
__device__ float g_X1  [2*MSZ];
__device__ float g_Tm  [2*MSZ];
__device__ float g_Wqkv[Cc*C3];
__device__ float g_W1p [Cc*PPAD];      // W1 re-packed to aligned stride 384
__device__ float g_part[NS_CTAS];
__device__ unsigned g_barCnt;
__device__ unsigned g_barGen;

// ================= software grid barrier =================
__device__ __forceinline__ void gridbar() {
    __syncthreads();
    if (threadIdx.x == 0) {
        __threadfence();
        volatile unsigned* vg = &g_barGen;
        unsigned gen = *vg;
        unsigned old = atomicAdd(&g_barCnt, 1u);
        if (old == NS_CTAS - 1) {
            g_barCnt = 0;
            __threadfence();
            *vg = gen + 1;
        } else {
            while (*vg == gen) { }
        }
        __threadfence();
    }
    __syncthreads();
}

// ================= persistent Newton-Schulz polar orthogonalization =================
__global__ __launch_bounds__(256)
void ns_k(const float* __restrict__ Win, const float* __restrict__ Wout)
{
    int bx = blockIdx.x, tid = threadIdx.x;
    int lane = tid & 31, wid = tid >> 5;
    int b  = bx / 72;
    int t  = bx % 72;
    int tm = t / 6;
    int tn = t % 6;
    int ty = tid >> 4;
    int tx = tid & 15;

    __shared__ float As[16][36];
    __shared__ float Bs[16][72];
    __shared__ float red[8];
    __shared__ float ssc[2];

    const float* W = b ? Wout : Win;

    {
        long off = (long)t * 2048;
        float ss = 0.f;
        #pragma unroll
        for (int i = 0; i < 8; i++) { float w = W[off + tid + i * 256]; ss += w * w; }
        #pragma unroll
        for (int o = 16; o > 0; o >>= 1) ss += __shfl_xor_sync(0xffffffffu, ss, o);
        if (lane == 0) red[wid] = ss;
        __syncthreads();
        if (tid == 0) {
            float s = 0.f;
            #pragma unroll
            for (int i = 0; i < 8; i++) s += red[i];
            __stcg(&g_part[bx], s);
        }
    }
    gridbar();

    if (tid < 2) {
        float s = 0.f;
        for (int i = 0; i < 72; i++) s += __ldcg(&g_part[tid * 72 + i]);
        ssc[tid] = rsqrtf(s);
    }
    __syncthreads();
    float rs = ssc[b];

    {
        long off = (long)t * 2048;
        #pragma unroll
        for (int i = 0; i < 8; i++)
            __stcg(&g_X0[(long)b * MSZ + off + tid + i * 256], W[off + tid + i * 256] * rs);
    }
    gridbar();

    float* Xc = g_X0;
    float* Xn = g_X1;

    for (int it = 0; it < NS_ITERS; it++) {
        const float* X = Xc + (long)b * MSZ;
        float* T       = g_Tm + (long)b * MSZ;

        float acc[2][4] = {};
        for (int k0 = 0; k0 < Cc; k0 += 16) {
            if (tid < 128) {
                int r = tid >> 2, q = tid & 3;
                float4 v = __ldcg((const float4*)(X + (long)(tm * 32 + r) * Cc + k0 + q * 4));
                As[q*4+0][r] = v.x; As[q*4+1][r] = v.y; As[q*4+2][r] = v.z; As[q*4+3][r] = v.w;
            }
            {
                int r = tid >> 2, q = tid & 3;
                float4 v = __ldcg((const float4*)(X + (long)(tn * 64 + r) * Cc + k0 + q * 4));
                Bs[q*4+0][r] = v.x; Bs[q*4+1][r] = v.y; Bs[q*4+2][r] = v.z; Bs[q*4+3][r] = v.w;
            }
            __syncthreads();
            #pragma unroll
            for (int k = 0; k < 16; k++) {
                float a0 = As[k][ty*2], a1 = As[k][ty*2+1];
                float b0 = Bs[k][tx*4], b1 = Bs[k][tx*4+1], b2 = Bs[k][tx*4+2], b3 = Bs[k][tx*4+3];
                acc[0][0] = fmaf(a0,b0,acc[0][0]); acc[0][1] = fmaf(a0,b1,acc[0][1]);
                acc[0][2] = fmaf(a0,b2,acc[0][2]); acc[0][3] = fmaf(a0,b3,acc[0][3]);
                acc[1][0] = fmaf(a1,b0,acc[1][0]); acc[1][1] = fmaf(a1,b1,acc[1][1]);
                acc[1][2] = fmaf(a1,b2,acc[1][2]); acc[1][3] = fmaf(a1,b3,acc[1][3]);
            }
            __syncthreads();
        }
        #pragma unroll
        for (int i = 0; i < 2; i++)
            #pragma unroll
            for (int j = 0; j < 4; j++)
                __stcg(&T[(long)(tm * 32 + ty * 2 + i) * Cc + tn * 64 + tx * 4 + j], acc[i][j]);
        gridbar();

        float ac2[2][4] = {};
        for (int k0 = 0; k0 < Cc; k0 += 16) {
            if (tid < 128) {
                int r = tid >> 2, q = tid & 3;
                float4 v = __ldcg((const float4*)(T + (long)(tm * 32 + r) * Cc + k0 + q * 4));
                As[q*4+0][r] = v.x; As[q*4+1][r] = v.y; As[q*4+2][r] = v.z; As[q*4+3][r] = v.w;
            }
            {
                int kk = tid >> 4, n4 = tid & 15;
                float4 v = __ldcg((const float4*)(X + (long)(k0 + kk) * Cc + tn * 64 + n4 * 4));
                Bs[kk][n4*4+0] = v.x; Bs[kk][n4*4+1] = v.y; Bs[kk][n4*4+2] = v.z; Bs[kk][n4*4+3] = v.w;
            }
            __syncthreads();
            #pragma unroll
            for (int k = 0; k < 16; k++) {
                float a0 = As[k][ty*2], a1 = As[k][ty*2+1];
                float b0 = Bs[k][tx*4], b1 = Bs[k][tx*4+1], b2 = Bs[k][tx*4+2], b3 = Bs[k][tx*4+3];
                ac2[0][0] = fmaf(a0,b0,ac2[0][0]); ac2[0][1] = fmaf(a0,b1,ac2[0][1]);
                ac2[0][2] = fmaf(a0,b2,ac2[0][2]); ac2[0][3] = fmaf(a0,b3,ac2[0][3]);
                ac2[1][0] = fmaf(a1,b0,ac2[1][0]); ac2[1][1] = fmaf(a1,b1,ac2[1][1]);
                ac2[1][2] = fmaf(a1,b2,ac2[1][2]); ac2[1][3] = fmaf(a1,b3,ac2[1][3]);
            }
            __syncthreads();
        }
        {
            float* Xnb = Xn + (long)b * MSZ;
            #pragma unroll
            for (int i = 0; i < 2; i++)
                #pragma unroll
                for (int j = 0; j < 4; j++) {
                    long idx = (long)(tm * 32 + ty * 2 + i) * Cc + tn * 64 + tx * 4 + j;
                    float xv = __ldcg(&X[idx]);
                    __stcg(&Xnb[idx], 1.5f * xv - 0.5f * ac2[i][j]);
                }
        }
        gridbar();
        float* tp = Xc; Xc = Xn; Xn = tp;
    }
}

// ================= tf32 mma primitives =================
__device__ __forceinline__ unsigned f2tf32(float f) {
    unsigned u; asm("cvt.rna.tf32.f32 %0, %1;" : "=r"(u) : "f"(f)); return u;
}
__device__ __forceinline__ void mma8(float* c, unsigned a0, unsigned a1, unsigned a2, unsigned a3,
                                     unsigned b0, unsigned b1) {
    asm volatile(
        "mma.sync.aligned.m16n8k8.row.col.f32.tf32.tf32.f32 "
        "{%0,%1,%2,%3}, {%4,%5,%6,%7}, {%8,%9}, {%0,%1,%2,%3};"
        : "+f"(c[0]), "+f"(c[1]), "+f"(c[2]), "+f"(c[3])
        : "r"(a0), "r"(a1), "r"(a2), "r"(a3), "r"(b0), "r"(b1));
}
__device__ __forceinline__ void cpa16(unsigned dst, const float* src, int bytes) {
    asm volatile("cp.async.cg.shared.global [%0], [%1], 16, %2;\n"
                 :: "r"(dst), "l"(src), "r"(bytes));
}
__device__ __forceinline__ void cpa_commit() {
    asm volatile("cp.async.commit_group;\n");
}
__device__ __forceinline__ void cpa_wait2() {
    asm volatile("cp.async.wait_group 2;\n");
}

// ===== tf32 GEMM, cp.async 4-stage: BM=128 BN=128 BK=16, 128 thr, 4 warps of 64x64 =====
// ALIGNMENT CONTRACT: A, B, lda, ldb must give 16B-aligned addresses (lda,ldb % 4 == 0).
#define STG 4
#define GA_SZ (128*20)
#define GB_SZ (16*136)
#define GS_SZ (GA_SZ + GB_SZ)
#define GEMM_SMEM (STG * GS_SZ * 4)

template<bool RELU, bool BIAS, bool RES>
__global__ __launch_bounds__(128, 2)
void gemm_ca(const float* __restrict__ A, const float* __restrict__ B,
             const float* __restrict__ bias, const float* __restrict__ Res,
             float* __restrict__ C,
             int Nstore, int K, int lda, int ldb, int Nreal, int Kb)
{
    extern __shared__ float smg[];
    unsigned smem_u32 = (unsigned)__cvta_generic_to_shared(smg);

    int tid = threadIdx.x;
    int lane = tid & 31, w = tid >> 5;
    int gr = lane >> 2, tg = lane & 3;
    int wm = w & 1, wn = w >> 1;          // warp tile rows wm*64, cols wn*64
    long m0 = (long)blockIdx.y * 128;
    int n0 = blockIdx.x * 128;

    // loaders
    int ar = tid >> 2, aq = tid & 3;      // A: rows ar + 32j, col aq*4
    int br = tid >> 5, bc = tid & 31;     // B: rows br + 4j, col bc*4
    int gn_b = n0 + bc * 4;
    int nbytes_col = 0;                   // bytes valid in this thread's B column granule
    {
        int rem = Nreal - gn_b;
        if (rem > 4) rem = 4;
        if (rem < 0) rem = 0;
        nbytes_col = rem * 4;
    }

    float acc[4][8][4];
    #pragma unroll
    for (int i = 0; i < 4; i++)
        #pragma unroll
        for (int j = 0; j < 8; j++)
            #pragma unroll
            for (int e = 0; e < 4; e++) acc[i][j][e] = 0.f;

    int nk = K / 16;

    auto issue = [&](int kt, int s) {
        int k0 = kt * 16;
        unsigned abase = smem_u32 + (s * GS_SZ) * 4;
        unsigned bbase = abase + GA_SZ * 4;
        #pragma unroll
        for (int j = 0; j < 4; j++) {
            int row = ar + j * 32;
            cpa16(abase + (row * 20 + aq * 4) * 4,
                  A + (m0 + row) * lda + k0 + aq * 4, 16);
        }
        #pragma unroll
        for (int j = 0; j < 4; j++) {
            int row = br + j * 4;
            int gk = k0 + row;
            int bytes = (gk < Kb) ? nbytes_col : 0;
            const float* src = (bytes > 0) ? (B + (long)gk * ldb + gn_b) : B;
            cpa16(bbase + (row * 136 + bc * 4) * 4, src, bytes);
        }
        cpa_commit();
    };

    // prologue: stages 0..2
    issue(0, 0);
    issue(1, 1);
    issue(2, 2);

    for (int kt = 0; kt < nk; kt++) {
        cpa_wait2();
        __syncthreads();

        if (kt + 3 < nk) issue(kt + 3, (kt + 3) & 3);
        else cpa_commit();   // keep group accounting aligned

        const float* As = smg + (kt & 3) * GS_SZ;
        const float* Bs = As + GA_SZ;

        #pragma unroll
        for (int ks = 0; ks < 2; ks++) {
            int kb = ks * 8;
            unsigned bf[8][2];
            #pragma unroll
            for (int nt = 0; nt < 8; nt++) {
                int ncol = wn * 64 + nt * 8;
                bf[nt][0] = f2tf32(Bs[(kb + tg    ) * 136 + ncol + gr]);
                bf[nt][1] = f2tf32(Bs[(kb + tg + 4) * 136 + ncol + gr]);
            }
            #pragma unroll
            for (int mt = 0; mt < 4; mt++) {
                int mrow = wm * 64 + mt * 16;
                unsigned a0 = f2tf32(As[(mrow + gr    ) * 20 + kb + tg    ]);
                unsigned a1 = f2tf32(As[(mrow + gr + 8) * 20 + kb + tg    ]);
                unsigned a2 = f2tf32(As[(mrow + gr    ) * 20 + kb + tg + 4]);
                unsigned a3 = f2tf32(As[(mrow + gr + 8) * 20 + kb + tg + 4]);
                #pragma unroll
                for (int nt = 0; nt < 8; nt++)
                    mma8(acc[mt][nt], a0, a1, a2, a3, bf[nt][0], bf[nt][1]);
            }
        }
        __syncthreads();
    }

    // epilogue
    #pragma unroll
    for (int mt = 0; mt < 4; mt++) {
        #pragma unroll
        for (int nt = 0; nt < 8; nt++) {
            int r0 = wm * 64 + mt * 16 + gr;
            int cb = n0 + wn * 64 + nt * 8 + 2 * tg;
            if (cb >= Nstore) continue;
            #pragma unroll
            for (int half = 0; half < 2; half++) {
                long gm = m0 + r0 + half * 8;
                float v0 = acc[mt][nt][half * 2 + 0];
                float v1 = acc[mt][nt][half * 2 + 1];
                if (BIAS) {
                    v0 += (cb     < Nreal) ? bias[cb]     : 0.f;
                    v1 += (cb + 1 < Nreal) ? bias[cb + 1] : 0.f;
                }
                if (RES) {
                    float2 rr = *(const float2*)(Res + gm * Nstore + cb);
                    v0 += rr.x; v1 += rr.y;
                }
                if (RELU) { v0 = fmaxf(v0, 0.f); v1 = fmaxf(v1, 0.f); }
                *(float2*)(C + gm * Nstore + cb) = make_float2(v0, v1);
            }
        }
    }
}

// ---------------- rmsnorm ----------------
__global__ __launch_bounds__(256)
void rmsnorm_k(const float* __restrict__ x, const float* __restrict__ scale,
               float* __restrict__ out)
{
    int warp = threadIdx.x >> 5, lane = threadIdx.x & 31;
    long t = (long)blockIdx.x * 8 + warp;
    const float* xr = x + t * Cc;
    float v[12], ss = 0.f;
    #pragma unroll
    for (int i = 0; i < 12; i++) { v[i] = xr[lane + i * 32]; ss += v[i] * v[i]; }
    #pragma unroll
    for (int o = 16; o > 0; o >>= 1) ss += __shfl_xor_sync(0xffffffffu, ss, o);
    float inv = rsqrtf(ss * (1.0f / Cc) + 1e-6f);
    float* orow = out + t * Cc;
    #pragma unroll
    for (int i = 0; i < 12; i++) orow[lane + i * 32] = v[i] * inv * scale[lane + i * 32];
}

// ---------------- pack Wqkv ----------------
__global__ void pack_k(const float* __restrict__ Wq, const float* __restrict__ Wk,
                       const float* __restrict__ Wv, float* __restrict__ Wqkv)
{
    int i = blockIdx.x * 256 + threadIdx.x;
    if (i >= Hh * Cc * HSs) return;
    int h = i / (Cc * HSs);
    int rem = i % (Cc * HSs);
    int c = rem / HSs, d = rem % HSs;
    long row = (long)c * C3;
    Wqkv[row +           h * HSs + d] = Wq[i];
    Wqkv[row + Cc      + h * HSs + d] = Wk[i];
    Wqkv[row + 2 * Cc  + h * HSs + d] = Wv[i];
}

// ---------------- pad W1 [C,307] -> [C,384] (16B-aligned rows; pad = 0) ----------------
__global__ void padW1_k(const float* __restrict__ W1, float* __restrict__ W1p)
{
    int i = blockIdx.x * 256 + threadIdx.x;
    if (i >= Cc * PPAD) return;
    int c = i / PPAD, p = i % PPAD;
    W1p[i] = (p < Pp) ? W1[(long)c * Pp + p] : 0.f;
}

// ================= tensor-core causal flash attention (tf32) =================
// grid (2, 6, 256), 256 thr = 8 warps. CTA: 128 q rows; warp w owns rows w*16..+16 (all 64 cols).
#define FQ 68
#define FV 72
#define FLASH_SMEM ((128*FQ + 64*FQ + 64*FV + 128*FQ) * 4)
__global__ __launch_bounds__(256, 2)
void flash_tc(const float* __restrict__ qkv, float* __restrict__ attn)
{
    extern __shared__ unsigned sm[];
    unsigned* Qs = sm;                 // [128][68]
    unsigned* Ks = Qs + 128 * FQ;      // [64][68]
    unsigned* Vs = Ks + 64 * FQ;       // [64][72]
    unsigned* Ps = Vs + 64 * FV;       // [128][68]

    int qb = blockIdx.x, h = blockIdx.y, b = blockIdx.z;
    int tid = threadIdx.x;
    int lane = tid & 31, w = tid >> 5;
    int gr = lane >> 2, tg = lane & 3;
    int wr = w * 16;

    long base = (long)b * Tt * C3 + (long)h * HSs;

    // stage Q (scaled) -> Qs
    for (int f = tid; f < 128 * 16; f += 256) {
        int row = f >> 4, d4 = f & 15;
        float4 v = *(const float4*)(qkv + base + (long)(qb * 128 + row) * C3 + d4 * 4);
        uint4 u = { f2tf32(v.x * 0.125f), f2tf32(v.y * 0.125f),
                    f2tf32(v.z * 0.125f), f2tf32(v.w * 0.125f) };
        *(uint4*)&Qs[row * FQ + d4 * 4] = u;
    }

    float oacc[8][4];
    #pragma unroll
    for (int i = 0; i < 8; i++)
        #pragma unroll
        for (int j = 0; j < 4; j++) oacc[i][j] = 0.f;
    float m0 = -1e30f, m1 = -1e30f, l0 = 0.f, l1 = 0.f;

    int r0g = qb * 128 + wr + gr;      // global q row (lower half)
    int r1g = r0g + 8;

    int ktmax = 2 * qb + 1;
    for (int kt = 0; kt <= ktmax; kt++) {
        __syncthreads();               // Qs staged (1st) / prior PV reads done
        for (int f = tid; f < 64 * 16; f += 256) {
            int row = f >> 4, d4 = f & 15;
            long off = base + (long)(kt * 64 + row) * C3 + d4 * 4;
            float4 kv = *(const float4*)(qkv + off + Cc);
            float4 vv = *(const float4*)(qkv + off + 2 * Cc);
            uint4 ku = { f2tf32(kv.x), f2tf32(kv.y), f2tf32(kv.z), f2tf32(kv.w) };
            uint4 vu = { f2tf32(vv.x), f2tf32(vv.y), f2tf32(vv.z), f2tf32(vv.w) };
            *(uint4*)&Ks[row * FQ + d4 * 4] = ku;
            *(uint4*)&Vs[row * FV + d4 * 4] = vu;
        }
        __syncthreads();

        // S = Q @ K^T  (warp: 16 rows x 64 cols)
        float sacc[8][4];
        #pragma unroll
        for (int i = 0; i < 8; i++)
            #pragma unroll
            for (int j = 0; j < 4; j++) sacc[i][j] = 0.f;
        #pragma unroll
        for (int ks = 0; ks < 8; ks++) {
            int kb = ks * 8;
            unsigned a0 = Qs[(wr + gr    ) * FQ + kb + tg    ];
            unsigned a1 = Qs[(wr + gr + 8) * FQ + kb + tg    ];
            unsigned a2 = Qs[(wr + gr    ) * FQ + kb + tg + 4];
            unsigned a3 = Qs[(wr + gr + 8) * FQ + kb + tg + 4];
            #pragma unroll
            for (int nt = 0; nt < 8; nt++) {
                unsigned b0 = Ks[(nt * 8 + gr) * FQ + kb + tg    ];
                unsigned b1 = Ks[(nt * 8 + gr) * FQ + kb + tg + 4];
                mma8(sacc[nt], a0, a1, a2, a3, b0, b1);
            }
        }

        // causal mask (global indices; full tiles unaffected)
        #pragma unroll
        for (int nt = 0; nt < 8; nt++) {
            int c = kt * 64 + nt * 8 + 2 * tg;
            if (c     > r0g) sacc[nt][0] = -1e30f;
            if (c + 1 > r0g) sacc[nt][1] = -1e30f;
            if (c     > r1g) sacc[nt][2] = -1e30f;
            if (c + 1 > r1g) sacc[nt][3] = -1e30f;
        }

        // warp-local online softmax (rows fully owned by warp)
        float mx0 = -1e30f, mx1 = -1e30f;
        #pragma unroll
        for (int nt = 0; nt < 8; nt++) {
            mx0 = fmaxf(mx0, fmaxf(sacc[nt][0], sacc[nt][1]));
            mx1 = fmaxf(mx1, fmaxf(sacc[nt][2], sacc[nt][3]));
        }
        mx0 = fmaxf(mx0, __shfl_xor_sync(0xffffffffu, mx0, 1));
        mx0 = fmaxf(mx0, __shfl_xor_sync(0xffffffffu, mx0, 2));
        mx1 = fmaxf(mx1, __shfl_xor_sync(0xffffffffu, mx1, 1));
        mx1 = fmaxf(mx1, __shfl_xor_sync(0xffffffffu, mx1, 2));
        float mn0 = fmaxf(m0, mx0), mn1 = fmaxf(m1, mx1);
        float corr0 = __expf(m0 - mn0), corr1 = __expf(m1 - mn1);

        float rs0 = 0.f, rs1 = 0.f;
        #pragma unroll
        for (int nt = 0; nt < 8; nt++) {
            sacc[nt][0] = __expf(sacc[nt][0] - mn0);
            sacc[nt][1] = __expf(sacc[nt][1] - mn0);
            sacc[nt][2] = __expf(sacc[nt][2] - mn1);
            sacc[nt][3] = __expf(sacc[nt][3] - mn1);
            rs0 += sacc[nt][0] + sacc[nt][1];
            rs1 += sacc[nt][2] + sacc[nt][3];
        }
        rs0 += __shfl_xor_sync(0xffffffffu, rs0, 1);
        rs0 += __shfl_xor_sync(0xffffffffu, rs0, 2);
        rs1 += __shfl_xor_sync(0xffffffffu, rs1, 1);
        rs1 += __shfl_xor_sync(0xffffffffu, rs1, 2);
        l0 = l0 * corr0 + rs0;
        l1 = l1 * corr1 + rs1;
        m0 = mn0; m1 = mn1;
        #pragma unroll
        for (int nt = 0; nt < 8; nt++) {
            oacc[nt][0] *= corr0; oacc[nt][1] *= corr0;
            oacc[nt][2] *= corr1; oacc[nt][3] *= corr1;
        }

        // store P (warp-private rows of Ps)
        #pragma unroll
        for (int nt = 0; nt < 8; nt++) {
            uint2 u0 = { f2tf32(sacc[nt][0]), f2tf32(sacc[nt][1]) };
            uint2 u1 = { f2tf32(sacc[nt][2]), f2tf32(sacc[nt][3]) };
            *(uint2*)&Ps[(wr + gr    ) * FQ + nt * 8 + 2 * tg] = u0;
            *(uint2*)&Ps[(wr + gr + 8) * FQ + nt * 8 + 2 * tg] = u1;
        }
        __syncwarp();

        // O += P @ V
        #pragma unroll
        for (int ks = 0; ks < 8; ks++) {
            int kb = ks * 8;
            unsigned pa0 = Ps[(wr + gr    ) * FQ + kb + tg    ];
            unsigned pa1 = Ps[(wr + gr + 8) * FQ + kb + tg    ];
            unsigned pa2 = Ps[(wr + gr    ) * FQ + kb + tg + 4];
            unsigned pa3 = Ps[(wr + gr + 8) * FQ + kb + tg + 4];
            #pragma unroll
            for (int nt = 0; nt < 8; nt++) {
                unsigned b0 = Vs[(kb + tg    ) * FV + nt * 8 + gr];
                unsigned b1 = Vs[(kb + tg + 4) * FV + nt * 8 + gr];
                mma8(oacc[nt], pa0, pa1, pa2, pa3, b0, b1);
            }
        }
    }

    float i0 = 1.f / l0, i1 = 1.f / l1;
    long orow0 = ((long)b * Tt + qb * 128 + wr + gr) * Cc + h * HSs;
    long orow1 = orow0 + 8L * Cc;
    #pragma unroll
    for (int nt = 0; nt < 8; nt++) {
        int c = nt * 8 + 2 * tg;
        *(float2*)(attn + orow0 + c) = make_float2(oacc[nt][0] * i0, oacc[nt][1] * i0);
        *(float2*)(attn + orow1 + c) = make_float2(oacc[nt][2] * i1, oacc[nt][3] * i1);
    }
}

// ---------------- host side ----------------
static float* symaddr(const void* sym) {
    void* p = nullptr;
    cudaGetSymbolAddress(&p, sym);
    return (float*)p;
}

extern "C" void kernel_launch(void* const* d_in, const int* in_sizes, int n_in,
                              void* d_out, int out_size)
{
    const float* x      = (const float*)d_in[0];
    const float* Wq     = (const float*)d_in[1];
    const float* Wk     = (const float*)d_in[2];
    const float* Wv     = (const float*)d_in[3];
    const float* Wp     = (const float*)d_in[4];
    const float* bp     = (const float*)d_in[5];
    const float* scale1 = (const float*)d_in[6];
    const float* scale2 = (const float*)d_in[7];
    const float* W1     = (const float*)d_in[8];
    const float* b1     = (const float*)d_in[9];
    const float* W2     = (const float*)d_in[10];
    const float* b2     = (const float*)d_in[11];
    const float* Wo_in  = (const float*)d_in[12];
    const float* Wo_out = (const float*)d_in[13];
    float* out = (float*)d_out;

    float* h1   = symaddr(g_h1);
    float* qkv  = symaddr(g_qkv);
    float* attn = symaddr(g_attn);
    float* h2   = symaddr(g_h2);
    float* h3   = symaddr(g_h3);
    float* h4   = symaddr(g_h4);
    float* ff   = symaddr(g_ff);
    float* h6   = symaddr(g_h6);
    float* X0   = symaddr(g_X0);
    float* Wqkv = symaddr(g_Wqkv);
    float* W1p  = symaddr(g_W1p);

    cudaFuncSetAttribute(flash_tc, cudaFuncAttributeMaxDynamicSharedMemorySize, FLASH_SMEM);
    cudaFuncSetAttribute(gemm_ca<false,false,false>, cudaFuncAttributeMaxDynamicSharedMemorySize, GEMM_SMEM);
    cudaFuncSetAttribute(gemm_ca<false,true,true>,   cudaFuncAttributeMaxDynamicSharedMemorySize, GEMM_SMEM);
    cudaFuncSetAttribute(gemm_ca<true,true,false>,   cudaFuncAttributeMaxDynamicSharedMemorySize, GEMM_SMEM);
    cudaFuncSetAttribute(gemm_ca<false,true,false>,  cudaFuncAttributeMaxDynamicSharedMemorySize, GEMM_SMEM);
    cudaFuncSetAttribute(gemm_ca<false,false,true>,  cudaFuncAttributeMaxDynamicSharedMemorySize, GEMM_SMEM);

    // ---- orth via persistent Newton-Schulz ----
    ns_k<<<NS_CTAS, 256>>>(Wo_in, Wo_out);
    const float* O_in  = X0;
    const float* O_out = X0 + MSZ;

    // ---- weight packing + ln1 ----
    pack_k<<<(Hh * Cc * HSs + 255) / 256, 256>>>(Wq, Wk, Wv, Wqkv);
    padW1_k<<<(Cc * PPAD + 255) / 256, 256>>>(W1, W1p);
    rmsnorm_k<<<BT / 8, 256>>>(x, scale1, h1);

    // ---- qkv = h1 @ Wqkv ----
    gemm_ca<false, false, false><<<dim3(C3 / 128, BT / 128), 128, GEMM_SMEM>>>(
        h1, Wqkv, nullptr, nullptr, qkv, C3, Cc, Cc, C3, C3, Cc);

    // ---- attention ----
    flash_tc<<<dim3(Tt / 128, Hh, Bb), 256, FLASH_SMEM>>>(qkv, attn);

    // ---- h2 = attn @ Wp + bp + h1 ----
    gemm_ca<false, true, true><<<dim3(Cc / 128, BT / 128), 128, GEMM_SMEM>>>(
        attn, Wp, bp, h1, h2, Cc, Cc, Cc, Cc, Cc, Cc);

    // ---- ln2 ----
    rmsnorm_k<<<BT / 8, 256>>>(h2, scale2, h3);

    // ---- h4 = h3 @ O_in ----
    gemm_ca<false, false, false><<<dim3(Cc / 128, BT / 128), 128, GEMM_SMEM>>>(
        h3, O_in, nullptr, nullptr, h4, Cc, Cc, Cc, Cc, Cc, Cc);

    // ---- ff = relu(h4 @ W1p + b1), W1p aligned stride 384; stored padded to 384 cols ----
    gemm_ca<true, true, false><<<dim3(PPAD / 128, BT / 128), 128, GEMM_SMEM>>>(
        h4, W1p, b1, nullptr, ff, PPAD, Cc, Cc, PPAD, Pp, Cc);

    // ---- h6 = ff @ W2 + b2  (pad cols of ff are zero; B rows guarded to 307) ----
    gemm_ca<false, true, false><<<dim3(Cc / 128, BT / 128), 128, GEMM_SMEM>>>(
        ff, W2, b2, nullptr, h6, Cc, PPAD, PPAD, Cc, Cc, Pp);

    // ---- out = h6 @ O_out + h6 ----
    gemm_ca<false, false, true><<<dim3(Cc / 128, BT / 128), 128, GEMM_SMEM>>>(
        h6, O_out, nullptr, h6, out, Cc, Cc, Cc, Cc, Cc, Cc);

    (void)in_sizes; (void)n_in; (void)out_size;
}

// round 11
// speedup vs baseline: 1.1910x; 1.0692x over previous
#include <cuda_runtime.h>

#define Bb  256
#define Tt  256
#define Cc  384
#define Hh  6
#define HSs 64
#define Pp  307
#define PPAD 384
#define BT  (Bb*Tt)            // 65536 tokens
#define C3  (3*Cc)             // 1152
#define NS_ITERS 36
#define NS_CTAS 144
#define MSZ (Cc*Cc)            // 147456

// ---------------- scratch (device globals; no allocation at runtime) ----------------
__device__ float g_h1  [(size_t)BT*Cc];
__device__ float g_qkv [(size_t)BT*C3];
__device__ float g_attn[(size_t)BT*Cc];
__device__ float g_h2  [(size_t)BT*Cc];
__device__ float g_h3  [(size_t)BT*Cc];
__device__ float g_ff  [(size_t)BT*PPAD];
__device__ float g_X0  [2*MSZ];
__device__ float g_X1  [2*MSZ];       // after ns_k: reused as W1f | W2f
__device__ float g_Tm  [2*MSZ];       // after ns_k: [0:MSZ] reused as W2p
__device__ float g_Wqkv[Cc*C3];
__device__ float g_W1p [Cc*PPAD];     // W1 re-packed to aligned stride 384
__device__ float g_b2f [Cc];
__device__ float g_part[NS_CTAS];
__device__ unsigned g_barCnt;
__device__ unsigned g_barGen;

// ================= software grid barrier =================
__device__ __forceinline__ void gridbar() {
    __syncthreads();
    if (threadIdx.x == 0) {
        __threadfence();
        volatile unsigned* vg = &g_barGen;
        unsigned gen = *vg;
        unsigned old = atomicAdd(&g_barCnt, 1u);
        if (old == NS_CTAS - 1) {
            g_barCnt = 0;
            __threadfence();
            *vg = gen + 1;
        } else {
            while (*vg == gen) { }
        }
        __threadfence();
    }
    __syncthreads();
}

// ================= persistent Newton-Schulz polar orthogonalization =================
__global__ __launch_bounds__(256)
void ns_k(const float* __restrict__ Win, const float* __restrict__ Wout)
{
    int bx = blockIdx.x, tid = threadIdx.x;
    int lane = tid & 31, wid = tid >> 5;
    int b  = bx / 72;
    int t  = bx % 72;
    int tm = t / 6;
    int tn = t % 6;
    int ty = tid >> 4;
    int tx = tid & 15;

    __shared__ float As[16][36];
    __shared__ float Bs[16][72];
    __shared__ float red[8];
    __shared__ float ssc[2];

    const float* W = b ? Wout : Win;

    {
        long off = (long)t * 2048;
        float ss = 0.f;
        #pragma unroll
        for (int i = 0; i < 8; i++) { float w = W[off + tid + i * 256]; ss += w * w; }
        #pragma unroll
        for (int o = 16; o > 0; o >>= 1) ss += __shfl_xor_sync(0xffffffffu, ss, o);
        if (lane == 0) red[wid] = ss;
        __syncthreads();
        if (tid == 0) {
            float s = 0.f;
            #pragma unroll
            for (int i = 0; i < 8; i++) s += red[i];
            __stcg(&g_part[bx], s);
        }
    }
    gridbar();

    if (tid < 2) {
        float s = 0.f;
        for (int i = 0; i < 72; i++) s += __ldcg(&g_part[tid * 72 + i]);
        ssc[tid] = rsqrtf(s);
    }
    __syncthreads();
    float rs = ssc[b];

    {
        long off = (long)t * 2048;
        #pragma unroll
        for (int i = 0; i < 8; i++)
            __stcg(&g_X0[(long)b * MSZ + off + tid + i * 256], W[off + tid + i * 256] * rs);
    }
    gridbar();

    float* Xc = g_X0;
    float* Xn = g_X1;

    for (int it = 0; it < NS_ITERS; it++) {
        const float* X = Xc + (long)b * MSZ;
        float* T       = g_Tm + (long)b * MSZ;

        float acc[2][4] = {};
        for (int k0 = 0; k0 < Cc; k0 += 16) {
            if (tid < 128) {
                int r = tid >> 2, q = tid & 3;
                float4 v = __ldcg((const float4*)(X + (long)(tm * 32 + r) * Cc + k0 + q * 4));
                As[q*4+0][r] = v.x; As[q*4+1][r] = v.y; As[q*4+2][r] = v.z; As[q*4+3][r] = v.w;
            }
            {
                int r = tid >> 2, q = tid & 3;
                float4 v = __ldcg((const float4*)(X + (long)(tn * 64 + r) * Cc + k0 + q * 4));
                Bs[q*4+0][r] = v.x; Bs[q*4+1][r] = v.y; Bs[q*4+2][r] = v.z; Bs[q*4+3][r] = v.w;
            }
            __syncthreads();
            #pragma unroll
            for (int k = 0; k < 16; k++) {
                float a0 = As[k][ty*2], a1 = As[k][ty*2+1];
                float b0 = Bs[k][tx*4], b1 = Bs[k][tx*4+1], b2 = Bs[k][tx*4+2], b3 = Bs[k][tx*4+3];
                acc[0][0] = fmaf(a0,b0,acc[0][0]); acc[0][1] = fmaf(a0,b1,acc[0][1]);
                acc[0][2] = fmaf(a0,b2,acc[0][2]); acc[0][3] = fmaf(a0,b3,acc[0][3]);
                acc[1][0] = fmaf(a1,b0,acc[1][0]); acc[1][1] = fmaf(a1,b1,acc[1][1]);
                acc[1][2] = fmaf(a1,b2,acc[1][2]); acc[1][3] = fmaf(a1,b3,acc[1][3]);
            }
            __syncthreads();
        }
        #pragma unroll
        for (int i = 0; i < 2; i++)
            #pragma unroll
            for (int j = 0; j < 4; j++)
                __stcg(&T[(long)(tm * 32 + ty * 2 + i) * Cc + tn * 64 + tx * 4 + j], acc[i][j]);
        gridbar();

        float ac2[2][4] = {};
        for (int k0 = 0; k0 < Cc; k0 += 16) {
            if (tid < 128) {
                int r = tid >> 2, q = tid & 3;
                float4 v = __ldcg((const float4*)(T + (long)(tm * 32 + r) * Cc + k0 + q * 4));
                As[q*4+0][r] = v.x; As[q*4+1][r] = v.y; As[q*4+2][r] = v.z; As[q*4+3][r] = v.w;
            }
            {
                int kk = tid >> 4, n4 = tid & 15;
                float4 v = __ldcg((const float4*)(X + (long)(k0 + kk) * Cc + tn * 64 + n4 * 4));
                Bs[kk][n4*4+0] = v.x; Bs[kk][n4*4+1] = v.y; Bs[kk][n4*4+2] = v.z; Bs[kk][n4*4+3] = v.w;
            }
            __syncthreads();
            #pragma unroll
            for (int k = 0; k < 16; k++) {
                float a0 = As[k][ty*2], a1 = As[k][ty*2+1];
                float b0 = Bs[k][tx*4], b1 = Bs[k][tx*4+1], b2 = Bs[k][tx*4+2], b3 = Bs[k][tx*4+3];
                ac2[0][0] = fmaf(a0,b0,ac2[0][0]); ac2[0][1] = fmaf(a0,b1,ac2[0][1]);
                ac2[0][2] = fmaf(a0,b2,ac2[0][2]); ac2[0][3] = fmaf(a0,b3,ac2[0][3]);
                ac2[1][0] = fmaf(a1,b0,ac2[1][0]); ac2[1][1] = fmaf(a1,b1,ac2[1][1]);
                ac2[1][2] = fmaf(a1,b2,ac2[1][2]); ac2[1][3] = fmaf(a1,b3,ac2[1][3]);
            }
            __syncthreads();
        }
        {
            float* Xnb = Xn + (long)b * MSZ;
            #pragma unroll
            for (int i = 0; i < 2; i++)
                #pragma unroll
                for (int j = 0; j < 4; j++) {
                    long idx = (long)(tm * 32 + ty * 2 + i) * Cc + tn * 64 + tx * 4 + j;
                    float xv = __ldcg(&X[idx]);
                    __stcg(&Xnb[idx], 1.5f * xv - 0.5f * ac2[i][j]);
                }
        }
        gridbar();
        float* tp = Xc; Xc = Xn; Xn = tp;
    }
}

// ================= tf32 mma primitives =================
__device__ __forceinline__ unsigned f2tf32(float f) {
    unsigned u; asm("cvt.rna.tf32.f32 %0, %1;" : "=r"(u) : "f"(f)); return u;
}
__device__ __forceinline__ void mma8(float* c, unsigned a0, unsigned a1, unsigned a2, unsigned a3,
                                     unsigned b0, unsigned b1) {
    asm volatile(
        "mma.sync.aligned.m16n8k8.row.col.f32.tf32.tf32.f32 "
        "{%0,%1,%2,%3}, {%4,%5,%6,%7}, {%8,%9}, {%0,%1,%2,%3};"
        : "+f"(c[0]), "+f"(c[1]), "+f"(c[2]), "+f"(c[3])
        : "r"(a0), "r"(a1), "r"(a2), "r"(a3), "r"(b0), "r"(b1));
}
__device__ __forceinline__ void cpa16(unsigned dst, const float* src, int bytes) {
    asm volatile("cp.async.cg.shared.global [%0], [%1], 16, %2;\n"
                 :: "r"(dst), "l"(src), "r"(bytes));
}
__device__ __forceinline__ void cpa_commit() {
    asm volatile("cp.async.commit_group;\n");
}
__device__ __forceinline__ void cpa_wait2() {
    asm volatile("cp.async.wait_group 2;\n");
}

// ===== tf32 GEMM, cp.async 4-stage: BM=128 BN=128 BK=16, 128 thr, 4 warps of 64x64 =====
// ALIGNMENT CONTRACT: A, B, lda, ldb must give 16B-aligned addresses (lda,ldb % 4 == 0).
#define STG 4
#define GA_SZ (128*20)
#define GB_SZ (16*136)
#define GS_SZ (GA_SZ + GB_SZ)
#define GEMM_SMEM (STG * GS_SZ * 4)

template<bool RELU, bool BIAS, bool RES>
__global__ __launch_bounds__(128, 2)
void gemm_ca(const float* __restrict__ A, const float* __restrict__ B,
             const float* __restrict__ bias, const float* __restrict__ Res,
             float* __restrict__ C,
             int Nstore, int K, int lda, int ldb, int Nreal, int Kb)
{
    extern __shared__ float smg[];
    unsigned smem_u32 = (unsigned)__cvta_generic_to_shared(smg);

    int tid = threadIdx.x;
    int lane = tid & 31, w = tid >> 5;
    int gr = lane >> 2, tg = lane & 3;
    int wm = w & 1, wn = w >> 1;          // warp tile rows wm*64, cols wn*64
    long m0 = (long)blockIdx.y * 128;
    int n0 = blockIdx.x * 128;

    // loaders
    int ar = tid >> 2, aq = tid & 3;      // A: rows ar + 32j, col aq*4
    int br = tid >> 5, bc = tid & 31;     // B: rows br + 4j, col bc*4
    int gn_b = n0 + bc * 4;
    int nbytes_col = 0;                   // bytes valid in this thread's B column granule
    {
        int rem = Nreal - gn_b;
        if (rem > 4) rem = 4;
        if (rem < 0) rem = 0;
        nbytes_col = rem * 4;
    }

    float acc[4][8][4];
    #pragma unroll
    for (int i = 0; i < 4; i++)
        #pragma unroll
        for (int j = 0; j < 8; j++)
            #pragma unroll
            for (int e = 0; e < 4; e++) acc[i][j][e] = 0.f;

    int nk = K / 16;

    auto issue = [&](int kt, int s) {
        int k0 = kt * 16;
        unsigned abase = smem_u32 + (s * GS_SZ) * 4;
        unsigned bbase = abase + GA_SZ * 4;
        #pragma unroll
        for (int j = 0; j < 4; j++) {
            int row = ar + j * 32;
            cpa16(abase + (row * 20 + aq * 4) * 4,
                  A + (m0 + row) * lda + k0 + aq * 4, 16);
        }
        #pragma unroll
        for (int j = 0; j < 4; j++) {
            int row = br + j * 4;
            int gk = k0 + row;
            int bytes = (gk < Kb) ? nbytes_col : 0;
            const float* src = (bytes > 0) ? (B + (long)gk * ldb + gn_b) : B;
            cpa16(bbase + (row * 136 + bc * 4) * 4, src, bytes);
        }
        cpa_commit();
    };

    // prologue: stages 0..2
    issue(0, 0);
    issue(1, 1);
    issue(2, 2);

    for (int kt = 0; kt < nk; kt++) {
        cpa_wait2();
        __syncthreads();

        if (kt + 3 < nk) issue(kt + 3, (kt + 3) & 3);
        else cpa_commit();   // keep group accounting aligned

        const float* As = smg + (kt & 3) * GS_SZ;
        const float* Bs = As + GA_SZ;

        #pragma unroll
        for (int ks = 0; ks < 2; ks++) {
            int kb = ks * 8;
            unsigned bf[8][2];
            #pragma unroll
            for (int nt = 0; nt < 8; nt++) {
                int ncol = wn * 64 + nt * 8;
                bf[nt][0] = f2tf32(Bs[(kb + tg    ) * 136 + ncol + gr]);
                bf[nt][1] = f2tf32(Bs[(kb + tg + 4) * 136 + ncol + gr]);
            }
            #pragma unroll
            for (int mt = 0; mt < 4; mt++) {
                int mrow = wm * 64 + mt * 16;
                unsigned a0 = f2tf32(As[(mrow + gr    ) * 20 + kb + tg    ]);
                unsigned a1 = f2tf32(As[(mrow + gr + 8) * 20 + kb + tg    ]);
                unsigned a2 = f2tf32(As[(mrow + gr    ) * 20 + kb + tg + 4]);
                unsigned a3 = f2tf32(As[(mrow + gr + 8) * 20 + kb + tg + 4]);
                #pragma unroll
                for (int nt = 0; nt < 8; nt++)
                    mma8(acc[mt][nt], a0, a1, a2, a3, bf[nt][0], bf[nt][1]);
            }
        }
        __syncthreads();
    }

    // epilogue
    #pragma unroll
    for (int mt = 0; mt < 4; mt++) {
        #pragma unroll
        for (int nt = 0; nt < 8; nt++) {
            int r0 = wm * 64 + mt * 16 + gr;
            int cb = n0 + wn * 64 + nt * 8 + 2 * tg;
            if (cb >= Nstore) continue;
            #pragma unroll
            for (int half = 0; half < 2; half++) {
                long gm = m0 + r0 + half * 8;
                float v0 = acc[mt][nt][half * 2 + 0];
                float v1 = acc[mt][nt][half * 2 + 1];
                if (BIAS) {
                    v0 += (cb     < Nreal) ? bias[cb]     : 0.f;
                    v1 += (cb + 1 < Nreal) ? bias[cb + 1] : 0.f;
                }
                if (RES) {
                    float2 rr = *(const float2*)(Res + gm * Nstore + cb);
                    v0 += rr.x; v1 += rr.y;
                }
                if (RELU) { v0 = fmaxf(v0, 0.f); v1 = fmaxf(v1, 0.f); }
                *(float2*)(C + gm * Nstore + cb) = make_float2(v0, v1);
            }
        }
    }
}

// ---------------- rmsnorm ----------------
__global__ __launch_bounds__(256)
void rmsnorm_k(const float* __restrict__ x, const float* __restrict__ scale,
               float* __restrict__ out)
{
    int warp = threadIdx.x >> 5, lane = threadIdx.x & 31;
    long t = (long)blockIdx.x * 8 + warp;
    const float* xr = x + t * Cc;
    float v[12], ss = 0.f;
    #pragma unroll
    for (int i = 0; i < 12; i++) { v[i] = xr[lane + i * 32]; ss += v[i] * v[i]; }
    #pragma unroll
    for (int o = 16; o > 0; o >>= 1) ss += __shfl_xor_sync(0xffffffffu, ss, o);
    float inv = rsqrtf(ss * (1.0f / Cc) + 1e-6f);
    float* orow = out + t * Cc;
    #pragma unroll
    for (int i = 0; i < 12; i++) orow[lane + i * 32] = v[i] * inv * scale[lane + i * 32];
}

// ---------------- pack Wqkv ----------------
__global__ void pack_k(const float* __restrict__ Wq, const float* __restrict__ Wk,
                       const float* __restrict__ Wv, float* __restrict__ Wqkv)
{
    int i = blockIdx.x * 256 + threadIdx.x;
    if (i >= Hh * Cc * HSs) return;
    int h = i / (Cc * HSs);
    int rem = i % (Cc * HSs);
    int c = rem / HSs, d = rem % HSs;
    long row = (long)c * C3;
    Wqkv[row +           h * HSs + d] = Wq[i];
    Wqkv[row + Cc      + h * HSs + d] = Wk[i];
    Wqkv[row + 2 * Cc  + h * HSs + d] = Wv[i];
}

// ---------------- pad W1 [C,307] -> [C,384] (pad cols = 0) ----------------
__global__ void padW1_k(const float* __restrict__ W1, float* __restrict__ W1p)
{
    int i = blockIdx.x * 256 + threadIdx.x;
    if (i >= Cc * PPAD) return;
    int c = i / PPAD, p = i % PPAD;
    W1p[i] = (p < Pp) ? W1[(long)c * Pp + p] : 0.f;
}

// ---------------- pad W2 [307,C] -> [384,C] (pad rows = 0) ----------------
__global__ void padW2_k(const float* __restrict__ W2, float* __restrict__ W2p)
{
    int i = blockIdx.x * 256 + threadIdx.x;
    if (i >= PPAD * Cc) return;
    int p = i / Cc;
    W2p[i] = (p < Pp) ? W2[i] : 0.f;
}

// ---------------- b2f = b2 @ O_out + b2 ----------------
__global__ void b2f_k(const float* __restrict__ b2, const float* __restrict__ O_out,
                      float* __restrict__ b2f)
{
    int j = blockIdx.x * 256 + threadIdx.x;
    if (j >= Cc) return;
    float s = b2[j];
    for (int k = 0; k < Cc; k++) s = fmaf(b2[k], O_out[(long)k * Cc + j], s);
    b2f[j] = s;
}

// ================= tensor-core causal flash attention (tf32) =================
// grid (2, 6, 256), 256 thr = 8 warps. CTA: 128 q rows; warp w owns rows w*16..+16 (all 64 cols).
#define FQ 68
#define FV 72
#define FLASH_SMEM ((128*FQ + 64*FQ + 64*FV + 128*FQ) * 4)
__global__ __launch_bounds__(256, 2)
void flash_tc(const float* __restrict__ qkv, float* __restrict__ attn)
{
    extern __shared__ unsigned sm[];
    unsigned* Qs = sm;                 // [128][68]
    unsigned* Ks = Qs + 128 * FQ;      // [64][68]
    unsigned* Vs = Ks + 64 * FQ;       // [64][72]
    unsigned* Ps = Vs + 64 * FV;       // [128][68]

    int qb = blockIdx.x, h = blockIdx.y, b = blockIdx.z;
    int tid = threadIdx.x;
    int lane = tid & 31, w = tid >> 5;
    int gr = lane >> 2, tg = lane & 3;
    int wr = w * 16;

    long base = (long)b * Tt * C3 + (long)h * HSs;

    // stage Q (scaled) -> Qs
    for (int f = tid; f < 128 * 16; f += 256) {
        int row = f >> 4, d4 = f & 15;
        float4 v = *(const float4*)(qkv + base + (long)(qb * 128 + row) * C3 + d4 * 4);
        uint4 u = { f2tf32(v.x * 0.125f), f2tf32(v.y * 0.125f),
                    f2tf32(v.z * 0.125f), f2tf32(v.w * 0.125f) };
        *(uint4*)&Qs[row * FQ + d4 * 4] = u;
    }

    float oacc[8][4];
    #pragma unroll
    for (int i = 0; i < 8; i++)
        #pragma unroll
        for (int j = 0; j < 4; j++) oacc[i][j] = 0.f;
    float m0 = -1e30f, m1 = -1e30f, l0 = 0.f, l1 = 0.f;

    int r0g = qb * 128 + wr + gr;      // global q row (lower half)
    int r1g = r0g + 8;

    int ktmax = 2 * qb + 1;
    for (int kt = 0; kt <= ktmax; kt++) {
        __syncthreads();               // Qs staged (1st) / prior PV reads done
        for (int f = tid; f < 64 * 16; f += 256) {
            int row = f >> 4, d4 = f & 15;
            long off = base + (long)(kt * 64 + row) * C3 + d4 * 4;
            float4 kv = *(const float4*)(qkv + off + Cc);
            float4 vv = *(const float4*)(qkv + off + 2 * Cc);
            uint4 ku = { f2tf32(kv.x), f2tf32(kv.y), f2tf32(kv.z), f2tf32(kv.w) };
            uint4 vu = { f2tf32(vv.x), f2tf32(vv.y), f2tf32(vv.z), f2tf32(vv.w) };
            *(uint4*)&Ks[row * FQ + d4 * 4] = ku;
            *(uint4*)&Vs[row * FV + d4 * 4] = vu;
        }
        __syncthreads();

        // S = Q @ K^T  (warp: 16 rows x 64 cols)
        float sacc[8][4];
        #pragma unroll
        for (int i = 0; i < 8; i++)
            #pragma unroll
            for (int j = 0; j < 4; j++) sacc[i][j] = 0.f;
        #pragma unroll
        for (int ks = 0; ks < 8; ks++) {
            int kb = ks * 8;
            unsigned a0 = Qs[(wr + gr    ) * FQ + kb + tg    ];
            unsigned a1 = Qs[(wr + gr + 8) * FQ + kb + tg    ];
            unsigned a2 = Qs[(wr + gr    ) * FQ + kb + tg + 4];
            unsigned a3 = Qs[(wr + gr + 8) * FQ + kb + tg + 4];
            #pragma unroll
            for (int nt = 0; nt < 8; nt++) {
                unsigned b0 = Ks[(nt * 8 + gr) * FQ + kb + tg    ];
                unsigned b1 = Ks[(nt * 8 + gr) * FQ + kb + tg + 4];
                mma8(sacc[nt], a0, a1, a2, a3, b0, b1);
            }
        }

        // causal mask (global indices; full tiles unaffected)
        #pragma unroll
        for (int nt = 0; nt < 8; nt++) {
            int c = kt * 64 + nt * 8 + 2 * tg;
            if (c     > r0g) sacc[nt][0] = -1e30f;
            if (c + 1 > r0g) sacc[nt][1] = -1e30f;
            if (c     > r1g) sacc[nt][2] = -1e30f;
            if (c + 1 > r1g) sacc[nt][3] = -1e30f;
        }

        // warp-local online softmax (rows fully owned by warp)
        float mx0 = -1e30f, mx1 = -1e30f;
        #pragma unroll
        for (int nt = 0; nt < 8; nt++) {
            mx0 = fmaxf(mx0, fmaxf(sacc[nt][0], sacc[nt][1]));
            mx1 = fmaxf(mx1, fmaxf(sacc[nt][2], sacc[nt][3]));
        }
        mx0 = fmaxf(mx0, __shfl_xor_sync(0xffffffffu, mx0, 1));
        mx0 = fmaxf(mx0, __shfl_xor_sync(0xffffffffu, mx0, 2));
        mx1 = fmaxf(mx1, __shfl_xor_sync(0xffffffffu, mx1, 1));
        mx1 = fmaxf(mx1, __shfl_xor_sync(0xffffffffu, mx1, 2));
        float mn0 = fmaxf(m0, mx0), mn1 = fmaxf(m1, mx1);
        float corr0 = __expf(m0 - mn0), corr1 = __expf(m1 - mn1);

        float rs0 = 0.f, rs1 = 0.f;
        #pragma unroll
        for (int nt = 0; nt < 8; nt++) {
            sacc[nt][0] = __expf(sacc[nt][0] - mn0);
            sacc[nt][1] = __expf(sacc[nt][1] - mn0);
            sacc[nt][2] = __expf(sacc[nt][2] - mn1);
            sacc[nt][3] = __expf(sacc[nt][3] - mn1);
            rs0 += sacc[nt][0] + sacc[nt][1];
            rs1 += sacc[nt][2] + sacc[nt][3];
        }
        rs0 += __shfl_xor_sync(0xffffffffu, rs0, 1);
        rs0 += __shfl_xor_sync(0xffffffffu, rs0, 2);
        rs1 += __shfl_xor_sync(0xffffffffu, rs1, 1);
        rs1 += __shfl_xor_sync(0xffffffffu, rs1, 2);
        l0 = l0 * corr0 + rs0;
        l1 = l1 * corr1 + rs1;
        m0 = mn0; m1 = mn1;
        #pragma unroll
        for (int nt = 0; nt < 8; nt++) {
            oacc[nt][0] *= corr0; oacc[nt][1] *= corr0;
            oacc[nt][2] *= corr1; oacc[nt][3] *= corr1;
        }

        // store P (warp-private rows of Ps)
        #pragma unroll
        for (int nt = 0; nt < 8; nt++) {
            uint2 u0 = { f2tf32(sacc[nt][0]), f2tf32(sacc[nt][1]) };
            uint2 u1 = { f2tf32(sacc[nt][2]), f2tf32(sacc[nt][3]) };
            *(uint2*)&Ps[(wr + gr    ) * FQ + nt * 8 + 2 * tg] = u0;
            *(uint2*)&Ps[(wr + gr + 8) * FQ + nt * 8 + 2 * tg] = u1;
        }
        __syncwarp();

        // O += P @ V
        #pragma unroll
        for (int ks = 0; ks < 8; ks++) {
            int kb = ks * 8;
            unsigned pa0 = Ps[(wr + gr    ) * FQ + kb + tg    ];
            unsigned pa1 = Ps[(wr + gr + 8) * FQ + kb + tg    ];
            unsigned pa2 = Ps[(wr + gr    ) * FQ + kb + tg + 4];
            unsigned pa3 = Ps[(wr + gr + 8) * FQ + kb + tg + 4];
            #pragma unroll
            for (int nt = 0; nt < 8; nt++) {
                unsigned b0 = Vs[(kb + tg    ) * FV + nt * 8 + gr];
                unsigned b1 = Vs[(kb + tg + 4) * FV + nt * 8 + gr];
                mma8(oacc[nt], pa0, pa1, pa2, pa3, b0, b1);
            }
        }
    }

    float i0 = 1.f / l0, i1 = 1.f / l1;
    long orow0 = ((long)b * Tt + qb * 128 + wr + gr) * Cc + h * HSs;
    long orow1 = orow0 + 8L * Cc;
    #pragma unroll
    for (int nt = 0; nt < 8; nt++) {
        int c = nt * 8 + 2 * tg;
        *(float2*)(attn + orow0 + c) = make_float2(oacc[nt][0] * i0, oacc[nt][1] * i0);
        *(float2*)(attn + orow1 + c) = make_float2(oacc[nt][2] * i1, oacc[nt][3] * i1);
    }
}

// ---------------- host side ----------------
static float* symaddr(const void* sym) {
    void* p = nullptr;
    cudaGetSymbolAddress(&p, sym);
    return (float*)p;
}

extern "C" void kernel_launch(void* const* d_in, const int* in_sizes, int n_in,
                              void* d_out, int out_size)
{
    const float* x      = (const float*)d_in[0];
    const float* Wq     = (const float*)d_in[1];
    const float* Wk     = (const float*)d_in[2];
    const float* Wv     = (const float*)d_in[3];
    const float* Wp     = (const float*)d_in[4];
    const float* bp     = (const float*)d_in[5];
    const float* scale1 = (const float*)d_in[6];
    const float* scale2 = (const float*)d_in[7];
    const float* W1     = (const float*)d_in[8];
    const float* b1     = (const float*)d_in[9];
    const float* W2     = (const float*)d_in[10];
    const float* b2     = (const float*)d_in[11];
    const float* Wo_in  = (const float*)d_in[12];
    const float* Wo_out = (const float*)d_in[13];
    float* out = (float*)d_out;

    float* h1   = symaddr(g_h1);
    float* qkv  = symaddr(g_qkv);
    float* attn = symaddr(g_attn);
    float* h2   = symaddr(g_h2);
    float* h3   = symaddr(g_h3);
    float* ff   = symaddr(g_ff);
    float* X0   = symaddr(g_X0);
    float* X1   = symaddr(g_X1);
    float* Tm   = symaddr(g_Tm);
    float* Wqkv = symaddr(g_Wqkv);
    float* W1p  = symaddr(g_W1p);
    float* b2f  = symaddr(g_b2f);

    cudaFuncSetAttribute(flash_tc, cudaFuncAttributeMaxDynamicSharedMemorySize, FLASH_SMEM);
    cudaFuncSetAttribute(gemm_ca<false,false,false>, cudaFuncAttributeMaxDynamicSharedMemorySize, GEMM_SMEM);
    cudaFuncSetAttribute(gemm_ca<false,true,true>,   cudaFuncAttributeMaxDynamicSharedMemorySize, GEMM_SMEM);
    cudaFuncSetAttribute(gemm_ca<true,true,false>,   cudaFuncAttributeMaxDynamicSharedMemorySize, GEMM_SMEM);
    cudaFuncSetAttribute(gemm_ca<false,true,false>,  cudaFuncAttributeMaxDynamicSharedMemorySize, GEMM_SMEM);
    cudaFuncSetAttribute(gemm_ca<false,false,true>,  cudaFuncAttributeMaxDynamicSharedMemorySize, GEMM_SMEM);

    // ---- orth via persistent Newton-Schulz ----
    ns_k<<<NS_CTAS, 256>>>(Wo_in, Wo_out);
    const float* O_in  = X0;           // result lives in g_X0 (NS_ITERS even)
    const float* O_out = X0 + MSZ;

    // ---- weight packing / padding ----
    pack_k<<<(Hh * Cc * HSs + 255) / 256, 256>>>(Wq, Wk, Wv, Wqkv);
    padW1_k<<<(Cc * PPAD + 255) / 256, 256>>>(W1, W1p);
    float* W2p = Tm;                   // reuse g_Tm (free after ns_k)
    padW2_k<<<(PPAD * Cc + 255) / 256, 256>>>(W2, W2p);

    // ---- fold orthogonal maps into FFN weights (reuse g_X1 as W1f|W2f) ----
    float* W1f = X1;                   // [Cc x PPAD] = O_in @ W1p
    float* W2f = X1 + MSZ;             // [PPAD x Cc] = W2p @ O_out + W2p
    gemm_ca<false, false, false><<<dim3(PPAD / 128, Cc / 128), 128, GEMM_SMEM>>>(
        O_in, W1p, nullptr, nullptr, W1f, PPAD, Cc, Cc, PPAD, PPAD, Cc);
    gemm_ca<false, false, true><<<dim3(Cc / 128, PPAD / 128), 128, GEMM_SMEM>>>(
        W2p, O_out, nullptr, W2p, W2f, Cc, Cc, Cc, Cc, Cc, Cc);
    b2f_k<<<(Cc + 255) / 256, 256>>>(b2, O_out, b2f);

    // ---- ln1 ----
    rmsnorm_k<<<BT / 8, 256>>>(x, scale1, h1);

    // ---- qkv = h1 @ Wqkv ----
    gemm_ca<false, false, false><<<dim3(C3 / 128, BT / 128), 128, GEMM_SMEM>>>(
        h1, Wqkv, nullptr, nullptr, qkv, C3, Cc, Cc, C3, C3, Cc);

    // ---- attention ----
    flash_tc<<<dim3(Tt / 128, Hh, Bb), 256, FLASH_SMEM>>>(qkv, attn);

    // ---- h2 = attn @ Wp + bp + h1 ----
    gemm_ca<false, true, true><<<dim3(Cc / 128, BT / 128), 128, GEMM_SMEM>>>(
        attn, Wp, bp, h1, h2, Cc, Cc, Cc, Cc, Cc, Cc);

    // ---- ln2 ----
    rmsnorm_k<<<BT / 8, 256>>>(h2, scale2, h3);

    // ---- ff = relu(h3 @ W1f + b1)  (O_in folded; bias guarded to 307 real cols) ----
    gemm_ca<true, true, false><<<dim3(PPAD / 128, BT / 128), 128, GEMM_SMEM>>>(
        h3, W1f, b1, nullptr, ff, PPAD, Cc, Cc, PPAD, Pp, Cc);

    // ---- out = ff @ W2f + b2f  (W2, O_out, +identity residual all folded) ----
    gemm_ca<false, true, false><<<dim3(Cc / 128, BT / 128), 128, GEMM_SMEM>>>(
        ff, W2f, b2f, nullptr, out, Cc, PPAD, PPAD, Cc, Cc, PPAD);

    (void)in_sizes; (void)n_in; (void)out_size;
}

// round 12
// speedup vs baseline: 1.2163x; 1.0213x over previous
#include <cuda_runtime.h>

#define Bb  256
#define Tt  256
#define Cc  384
#define Hh  6
#define HSs 64
#define Pp  307
#define PPAD 384
#define BT  (Bb*Tt)            // 65536 tokens
#define C3  (3*Cc)             // 1152
#define NS_ITERS 36
#define NS_CTAS 144
#define MSZ (Cc*Cc)            // 147456

// ---------------- scratch (device globals; no allocation at runtime) ----------------
__device__ float g_h1  [(size_t)BT*Cc];
__device__ float g_qkv [(size_t)BT*C3];
__device__ float g_attn[(size_t)BT*Cc];
__device__ float g_h2  [(size_t)BT*Cc];
__device__ float g_h3  [(size_t)BT*Cc];
__device__ float g_ff  [(size_t)BT*PPAD];
__device__ float g_X0  [2*MSZ];
__device__ float g_X1  [2*MSZ];       // after ns_k: reused as W1f | W2f
__device__ float g_Tm  [2*MSZ];       // ns_k private scratch
__device__ float g_W2p [PPAD*Cc];     // padded W2 (own buffer: may fill while ns_k runs)
__device__ float g_Wqkv[Cc*C3];
__device__ float g_W1p [Cc*PPAD];     // W1 re-packed to aligned stride 384
__device__ float g_b2f [Cc];
__device__ float g_part[NS_CTAS];
__device__ unsigned g_barCnt;
__device__ unsigned g_barGen;

// ================= software grid barrier =================
__device__ __forceinline__ void gridbar() {
    __syncthreads();
    if (threadIdx.x == 0) {
        __threadfence();
        volatile unsigned* vg = &g_barGen;
        unsigned gen = *vg;
        unsigned old = atomicAdd(&g_barCnt, 1u);
        if (old == NS_CTAS - 1) {
            g_barCnt = 0;
            __threadfence();
            *vg = gen + 1;
        } else {
            while (*vg == gen) { }
        }
        __threadfence();
    }
    __syncthreads();
}

// ================= persistent Newton-Schulz polar orthogonalization =================
__global__ __launch_bounds__(256)
void ns_k(const float* __restrict__ Win, const float* __restrict__ Wout)
{
    int bx = blockIdx.x, tid = threadIdx.x;
    int lane = tid & 31, wid = tid >> 5;
    int b  = bx / 72;
    int t  = bx % 72;
    int tm = t / 6;
    int tn = t % 6;
    int ty = tid >> 4;
    int tx = tid & 15;

    __shared__ float As[16][36];
    __shared__ float Bs[16][72];
    __shared__ float red[8];
    __shared__ float ssc[2];

    const float* W = b ? Wout : Win;

    {
        long off = (long)t * 2048;
        float ss = 0.f;
        #pragma unroll
        for (int i = 0; i < 8; i++) { float w = W[off + tid + i * 256]; ss += w * w; }
        #pragma unroll
        for (int o = 16; o > 0; o >>= 1) ss += __shfl_xor_sync(0xffffffffu, ss, o);
        if (lane == 0) red[wid] = ss;
        __syncthreads();
        if (tid == 0) {
            float s = 0.f;
            #pragma unroll
            for (int i = 0; i < 8; i++) s += red[i];
            __stcg(&g_part[bx], s);
        }
    }
    gridbar();

    if (tid < 2) {
        float s = 0.f;
        for (int i = 0; i < 72; i++) s += __ldcg(&g_part[tid * 72 + i]);
        ssc[tid] = rsqrtf(s);
    }
    __syncthreads();
    float rs = ssc[b];

    {
        long off = (long)t * 2048;
        #pragma unroll
        for (int i = 0; i < 8; i++)
            __stcg(&g_X0[(long)b * MSZ + off + tid + i * 256], W[off + tid + i * 256] * rs);
    }
    gridbar();

    float* Xc = g_X0;
    float* Xn = g_X1;

    for (int it = 0; it < NS_ITERS; it++) {
        const float* X = Xc + (long)b * MSZ;
        float* T       = g_Tm + (long)b * MSZ;

        float acc[2][4] = {};
        for (int k0 = 0; k0 < Cc; k0 += 16) {
            if (tid < 128) {
                int r = tid >> 2, q = tid & 3;
                float4 v = __ldcg((const float4*)(X + (long)(tm * 32 + r) * Cc + k0 + q * 4));
                As[q*4+0][r] = v.x; As[q*4+1][r] = v.y; As[q*4+2][r] = v.z; As[q*4+3][r] = v.w;
            }
            {
                int r = tid >> 2, q = tid & 3;
                float4 v = __ldcg((const float4*)(X + (long)(tn * 64 + r) * Cc + k0 + q * 4));
                Bs[q*4+0][r] = v.x; Bs[q*4+1][r] = v.y; Bs[q*4+2][r] = v.z; Bs[q*4+3][r] = v.w;
            }
            __syncthreads();
            #pragma unroll
            for (int k = 0; k < 16; k++) {
                float a0 = As[k][ty*2], a1 = As[k][ty*2+1];
                float b0 = Bs[k][tx*4], b1 = Bs[k][tx*4+1], b2 = Bs[k][tx*4+2], b3 = Bs[k][tx*4+3];
                acc[0][0] = fmaf(a0,b0,acc[0][0]); acc[0][1] = fmaf(a0,b1,acc[0][1]);
                acc[0][2] = fmaf(a0,b2,acc[0][2]); acc[0][3] = fmaf(a0,b3,acc[0][3]);
                acc[1][0] = fmaf(a1,b0,acc[1][0]); acc[1][1] = fmaf(a1,b1,acc[1][1]);
                acc[1][2] = fmaf(a1,b2,acc[1][2]); acc[1][3] = fmaf(a1,b3,acc[1][3]);
            }
            __syncthreads();
        }
        #pragma unroll
        for (int i = 0; i < 2; i++)
            #pragma unroll
            for (int j = 0; j < 4; j++)
                __stcg(&T[(long)(tm * 32 + ty * 2 + i) * Cc + tn * 64 + tx * 4 + j], acc[i][j]);
        gridbar();

        float ac2[2][4] = {};
        for (int k0 = 0; k0 < Cc; k0 += 16) {
            if (tid < 128) {
                int r = tid >> 2, q = tid & 3;
                float4 v = __ldcg((const float4*)(T + (long)(tm * 32 + r) * Cc + k0 + q * 4));
                As[q*4+0][r] = v.x; As[q*4+1][r] = v.y; As[q*4+2][r] = v.z; As[q*4+3][r] = v.w;
            }
            {
                int kk = tid >> 4, n4 = tid & 15;
                float4 v = __ldcg((const float4*)(X + (long)(k0 + kk) * Cc + tn * 64 + n4 * 4));
                Bs[kk][n4*4+0] = v.x; Bs[kk][n4*4+1] = v.y; Bs[kk][n4*4+2] = v.z; Bs[kk][n4*4+3] = v.w;
            }
            __syncthreads();
            #pragma unroll
            for (int k = 0; k < 16; k++) {
                float a0 = As[k][ty*2], a1 = As[k][ty*2+1];
                float b0 = Bs[k][tx*4], b1 = Bs[k][tx*4+1], b2 = Bs[k][tx*4+2], b3 = Bs[k][tx*4+3];
                ac2[0][0] = fmaf(a0,b0,ac2[0][0]); ac2[0][1] = fmaf(a0,b1,ac2[0][1]);
                ac2[0][2] = fmaf(a0,b2,ac2[0][2]); ac2[0][3] = fmaf(a0,b3,ac2[0][3]);
                ac2[1][0] = fmaf(a1,b0,ac2[1][0]); ac2[1][1] = fmaf(a1,b1,ac2[1][1]);
                ac2[1][2] = fmaf(a1,b2,ac2[1][2]); ac2[1][3] = fmaf(a1,b3,ac2[1][3]);
            }
            __syncthreads();
        }
        {
            float* Xnb = Xn + (long)b * MSZ;
            #pragma unroll
            for (int i = 0; i < 2; i++)
                #pragma unroll
                for (int j = 0; j < 4; j++) {
                    long idx = (long)(tm * 32 + ty * 2 + i) * Cc + tn * 64 + tx * 4 + j;
                    float xv = __ldcg(&X[idx]);
                    __stcg(&Xnb[idx], 1.5f * xv - 0.5f * ac2[i][j]);
                }
        }
        gridbar();
        float* tp = Xc; Xc = Xn; Xn = tp;
    }
}

// ================= tf32 mma primitives =================
__device__ __forceinline__ unsigned f2tf32(float f) {
    unsigned u; asm("cvt.rna.tf32.f32 %0, %1;" : "=r"(u) : "f"(f)); return u;
}
__device__ __forceinline__ void mma8(float* c, unsigned a0, unsigned a1, unsigned a2, unsigned a3,
                                     unsigned b0, unsigned b1) {
    asm volatile(
        "mma.sync.aligned.m16n8k8.row.col.f32.tf32.tf32.f32 "
        "{%0,%1,%2,%3}, {%4,%5,%6,%7}, {%8,%9}, {%0,%1,%2,%3};"
        : "+f"(c[0]), "+f"(c[1]), "+f"(c[2]), "+f"(c[3])
        : "r"(a0), "r"(a1), "r"(a2), "r"(a3), "r"(b0), "r"(b1));
}
__device__ __forceinline__ void cpa16(unsigned dst, const float* src, int bytes) {
    asm volatile("cp.async.cg.shared.global [%0], [%1], 16, %2;\n"
                 :: "r"(dst), "l"(src), "r"(bytes));
}
__device__ __forceinline__ void cpa_commit() {
    asm volatile("cp.async.commit_group;\n");
}
__device__ __forceinline__ void cpa_wait2() {
    asm volatile("cp.async.wait_group 2;\n");
}

// ===== tf32 GEMM, cp.async 4-stage: BM=128 BN=128 BK=16, 128 thr, 4 warps of 64x64 =====
// ALIGNMENT CONTRACT: A, B, lda, ldb must give 16B-aligned addresses (lda,ldb % 4 == 0).
#define STG 4
#define GA_SZ (128*20)
#define GB_SZ (16*136)
#define GS_SZ (GA_SZ + GB_SZ)
#define GEMM_SMEM (STG * GS_SZ * 4)

template<bool RELU, bool BIAS, bool RES>
__global__ __launch_bounds__(128, 2)
void gemm_ca(const float* __restrict__ A, const float* __restrict__ B,
             const float* __restrict__ bias, const float* __restrict__ Res,
             float* __restrict__ C,
             int Nstore, int K, int lda, int ldb, int Nreal, int Kb)
{
    extern __shared__ float smg[];
    unsigned smem_u32 = (unsigned)__cvta_generic_to_shared(smg);

    int tid = threadIdx.x;
    int lane = tid & 31, w = tid >> 5;
    int gr = lane >> 2, tg = lane & 3;
    int wm = w & 1, wn = w >> 1;          // warp tile rows wm*64, cols wn*64
    long m0 = (long)blockIdx.y * 128;
    int n0 = blockIdx.x * 128;

    // loaders
    int ar = tid >> 2, aq = tid & 3;      // A: rows ar + 32j, col aq*4
    int br = tid >> 5, bc = tid & 31;     // B: rows br + 4j, col bc*4
    int gn_b = n0 + bc * 4;
    int nbytes_col = 0;                   // bytes valid in this thread's B column granule
    {
        int rem = Nreal - gn_b;
        if (rem > 4) rem = 4;
        if (rem < 0) rem = 0;
        nbytes_col = rem * 4;
    }

    float acc[4][8][4];
    #pragma unroll
    for (int i = 0; i < 4; i++)
        #pragma unroll
        for (int j = 0; j < 8; j++)
            #pragma unroll
            for (int e = 0; e < 4; e++) acc[i][j][e] = 0.f;

    int nk = K / 16;

    auto issue = [&](int kt, int s) {
        int k0 = kt * 16;
        unsigned abase = smem_u32 + (s * GS_SZ) * 4;
        unsigned bbase = abase + GA_SZ * 4;
        #pragma unroll
        for (int j = 0; j < 4; j++) {
            int row = ar + j * 32;
            cpa16(abase + (row * 20 + aq * 4) * 4,
                  A + (m0 + row) * lda + k0 + aq * 4, 16);
        }
        #pragma unroll
        for (int j = 0; j < 4; j++) {
            int row = br + j * 4;
            int gk = k0 + row;
            int bytes = (gk < Kb) ? nbytes_col : 0;
            const float* src = (bytes > 0) ? (B + (long)gk * ldb + gn_b) : B;
            cpa16(bbase + (row * 136 + bc * 4) * 4, src, bytes);
        }
        cpa_commit();
    };

    // prologue: stages 0..2
    issue(0, 0);
    issue(1, 1);
    issue(2, 2);

    for (int kt = 0; kt < nk; kt++) {
        cpa_wait2();
        __syncthreads();

        if (kt + 3 < nk) issue(kt + 3, (kt + 3) & 3);
        else cpa_commit();   // keep group accounting aligned

        const float* As = smg + (kt & 3) * GS_SZ;
        const float* Bs = As + GA_SZ;

        #pragma unroll
        for (int ks = 0; ks < 2; ks++) {
            int kb = ks * 8;
            unsigned bf[8][2];
            #pragma unroll
            for (int nt = 0; nt < 8; nt++) {
                int ncol = wn * 64 + nt * 8;
                bf[nt][0] = f2tf32(Bs[(kb + tg    ) * 136 + ncol + gr]);
                bf[nt][1] = f2tf32(Bs[(kb + tg + 4) * 136 + ncol + gr]);
            }
            #pragma unroll
            for (int mt = 0; mt < 4; mt++) {
                int mrow = wm * 64 + mt * 16;
                unsigned a0 = f2tf32(As[(mrow + gr    ) * 20 + kb + tg    ]);
                unsigned a1 = f2tf32(As[(mrow + gr + 8) * 20 + kb + tg    ]);
                unsigned a2 = f2tf32(As[(mrow + gr    ) * 20 + kb + tg + 4]);
                unsigned a3 = f2tf32(As[(mrow + gr + 8) * 20 + kb + tg + 4]);
                #pragma unroll
                for (int nt = 0; nt < 8; nt++)
                    mma8(acc[mt][nt], a0, a1, a2, a3, bf[nt][0], bf[nt][1]);
            }
        }
        __syncthreads();
    }

    // epilogue
    #pragma unroll
    for (int mt = 0; mt < 4; mt++) {
        #pragma unroll
        for (int nt = 0; nt < 8; nt++) {
            int r0 = wm * 64 + mt * 16 + gr;
            int cb = n0 + wn * 64 + nt * 8 + 2 * tg;
            if (cb >= Nstore) continue;
            #pragma unroll
            for (int half = 0; half < 2; half++) {
                long gm = m0 + r0 + half * 8;
                float v0 = acc[mt][nt][half * 2 + 0];
                float v1 = acc[mt][nt][half * 2 + 1];
                if (BIAS) {
                    v0 += (cb     < Nreal) ? bias[cb]     : 0.f;
                    v1 += (cb + 1 < Nreal) ? bias[cb + 1] : 0.f;
                }
                if (RES) {
                    float2 rr = *(const float2*)(Res + gm * Nstore + cb);
                    v0 += rr.x; v1 += rr.y;
                }
                if (RELU) { v0 = fmaxf(v0, 0.f); v1 = fmaxf(v1, 0.f); }
                *(float2*)(C + gm * Nstore + cb) = make_float2(v0, v1);
            }
        }
    }
}

// ---------------- rmsnorm ----------------
__global__ __launch_bounds__(256)
void rmsnorm_k(const float* __restrict__ x, const float* __restrict__ scale,
               float* __restrict__ out)
{
    int warp = threadIdx.x >> 5, lane = threadIdx.x & 31;
    long t = (long)blockIdx.x * 8 + warp;
    const float* xr = x + t * Cc;
    float v[12], ss = 0.f;
    #pragma unroll
    for (int i = 0; i < 12; i++) { v[i] = xr[lane + i * 32]; ss += v[i] * v[i]; }
    #pragma unroll
    for (int o = 16; o > 0; o >>= 1) ss += __shfl_xor_sync(0xffffffffu, ss, o);
    float inv = rsqrtf(ss * (1.0f / Cc) + 1e-6f);
    float* orow = out + t * Cc;
    #pragma unroll
    for (int i = 0; i < 12; i++) orow[lane + i * 32] = v[i] * inv * scale[lane + i * 32];
}

// ---------------- pack Wqkv ----------------
__global__ void pack_k(const float* __restrict__ Wq, const float* __restrict__ Wk,
                       const float* __restrict__ Wv, float* __restrict__ Wqkv)
{
    int i = blockIdx.x * 256 + threadIdx.x;
    if (i >= Hh * Cc * HSs) return;
    int h = i / (Cc * HSs);
    int rem = i % (Cc * HSs);
    int c = rem / HSs, d = rem % HSs;
    long row = (long)c * C3;
    Wqkv[row +           h * HSs + d] = Wq[i];
    Wqkv[row + Cc      + h * HSs + d] = Wk[i];
    Wqkv[row + 2 * Cc  + h * HSs + d] = Wv[i];
}

// ---------------- pad W1 [C,307] -> [C,384] (pad cols = 0) ----------------
__global__ void padW1_k(const float* __restrict__ W1, float* __restrict__ W1p)
{
    int i = blockIdx.x * 256 + threadIdx.x;
    if (i >= Cc * PPAD) return;
    int c = i / PPAD, p = i % PPAD;
    W1p[i] = (p < Pp) ? W1[(long)c * Pp + p] : 0.f;
}

// ---------------- pad W2 [307,C] -> [384,C] (pad rows = 0) ----------------
__global__ void padW2_k(const float* __restrict__ W2, float* __restrict__ W2p)
{
    int i = blockIdx.x * 256 + threadIdx.x;
    if (i >= PPAD * Cc) return;
    int p = i / Cc;
    W2p[i] = (p < Pp) ? W2[i] : 0.f;
}

// ---------------- b2f = b2 @ O_out + b2 ----------------
__global__ void b2f_k(const float* __restrict__ b2, const float* __restrict__ O_out,
                      float* __restrict__ b2f)
{
    int j = blockIdx.x * 256 + threadIdx.x;
    if (j >= Cc) return;
    float s = b2[j];
    for (int k = 0; k < Cc; k++) s = fmaf(b2[k], O_out[(long)k * Cc + j], s);
    b2f[j] = s;
}

// ================= tensor-core causal flash attention (tf32) =================
// grid (2, 6, 256), 256 thr = 8 warps. CTA: 128 q rows; warp w owns rows w*16..+16 (all 64 cols).
#define FQ 68
#define FV 72
#define FLASH_SMEM ((128*FQ + 64*FQ + 64*FV + 128*FQ) * 4)
__global__ __launch_bounds__(256, 2)
void flash_tc(const float* __restrict__ qkv, float* __restrict__ attn)
{
    extern __shared__ unsigned sm[];
    unsigned* Qs = sm;                 // [128][68]
    unsigned* Ks = Qs + 128 * FQ;      // [64][68]
    unsigned* Vs = Ks + 64 * FQ;       // [64][72]
    unsigned* Ps = Vs + 64 * FV;       // [128][68]

    int qb = blockIdx.x, h = blockIdx.y, b = blockIdx.z;
    int tid = threadIdx.x;
    int lane = tid & 31, w = tid >> 5;
    int gr = lane >> 2, tg = lane & 3;
    int wr = w * 16;

    long base = (long)b * Tt * C3 + (long)h * HSs;

    // stage Q (scaled) -> Qs
    for (int f = tid; f < 128 * 16; f += 256) {
        int row = f >> 4, d4 = f & 15;
        float4 v = *(const float4*)(qkv + base + (long)(qb * 128 + row) * C3 + d4 * 4);
        uint4 u = { f2tf32(v.x * 0.125f), f2tf32(v.y * 0.125f),
                    f2tf32(v.z * 0.125f), f2tf32(v.w * 0.125f) };
        *(uint4*)&Qs[row * FQ + d4 * 4] = u;
    }

    float oacc[8][4];
    #pragma unroll
    for (int i = 0; i < 8; i++)
        #pragma unroll
        for (int j = 0; j < 4; j++) oacc[i][j] = 0.f;
    float m0 = -1e30f, m1 = -1e30f, l0 = 0.f, l1 = 0.f;

    int r0g = qb * 128 + wr + gr;      // global q row (lower half)
    int r1g = r0g + 8;

    int ktmax = 2 * qb + 1;
    for (int kt = 0; kt <= ktmax; kt++) {
        __syncthreads();               // Qs staged (1st) / prior PV reads done
        for (int f = tid; f < 64 * 16; f += 256) {
            int row = f >> 4, d4 = f & 15;
            long off = base + (long)(kt * 64 + row) * C3 + d4 * 4;
            float4 kv = *(const float4*)(qkv + off + Cc);
            float4 vv = *(const float4*)(qkv + off + 2 * Cc);
            uint4 ku = { f2tf32(kv.x), f2tf32(kv.y), f2tf32(kv.z), f2tf32(kv.w) };
            uint4 vu = { f2tf32(vv.x), f2tf32(vv.y), f2tf32(vv.z), f2tf32(vv.w) };
            *(uint4*)&Ks[row * FQ + d4 * 4] = ku;
            *(uint4*)&Vs[row * FV + d4 * 4] = vu;
        }
        __syncthreads();

        // S = Q @ K^T  (warp: 16 rows x 64 cols)
        float sacc[8][4];
        #pragma unroll
        for (int i = 0; i < 8; i++)
            #pragma unroll
            for (int j = 0; j < 4; j++) sacc[i][j] = 0.f;
        #pragma unroll
        for (int ks = 0; ks < 8; ks++) {
            int kb = ks * 8;
            unsigned a0 = Qs[(wr + gr    ) * FQ + kb + tg    ];
            unsigned a1 = Qs[(wr + gr + 8) * FQ + kb + tg    ];
            unsigned a2 = Qs[(wr + gr    ) * FQ + kb + tg + 4];
            unsigned a3 = Qs[(wr + gr + 8) * FQ + kb + tg + 4];
            #pragma unroll
            for (int nt = 0; nt < 8; nt++) {
                unsigned b0 = Ks[(nt * 8 + gr) * FQ + kb + tg    ];
                unsigned b1 = Ks[(nt * 8 + gr) * FQ + kb + tg + 4];
                mma8(sacc[nt], a0, a1, a2, a3, b0, b1);
            }
        }

        // causal mask (global indices; full tiles unaffected)
        #pragma unroll
        for (int nt = 0; nt < 8; nt++) {
            int c = kt * 64 + nt * 8 + 2 * tg;
            if (c     > r0g) sacc[nt][0] = -1e30f;
            if (c + 1 > r0g) sacc[nt][1] = -1e30f;
            if (c     > r1g) sacc[nt][2] = -1e30f;
            if (c + 1 > r1g) sacc[nt][3] = -1e30f;
        }

        // warp-local online softmax (rows fully owned by warp)
        float mx0 = -1e30f, mx1 = -1e30f;
        #pragma unroll
        for (int nt = 0; nt < 8; nt++) {
            mx0 = fmaxf(mx0, fmaxf(sacc[nt][0], sacc[nt][1]));
            mx1 = fmaxf(mx1, fmaxf(sacc[nt][2], sacc[nt][3]));
        }
        mx0 = fmaxf(mx0, __shfl_xor_sync(0xffffffffu, mx0, 1));
        mx0 = fmaxf(mx0, __shfl_xor_sync(0xffffffffu, mx0, 2));
        mx1 = fmaxf(mx1, __shfl_xor_sync(0xffffffffu, mx1, 1));
        mx1 = fmaxf(mx1, __shfl_xor_sync(0xffffffffu, mx1, 2));
        float mn0 = fmaxf(m0, mx0), mn1 = fmaxf(m1, mx1);
        float corr0 = __expf(m0 - mn0), corr1 = __expf(m1 - mn1);

        float rs0 = 0.f, rs1 = 0.f;
        #pragma unroll
        for (int nt = 0; nt < 8; nt++) {
            sacc[nt][0] = __expf(sacc[nt][0] - mn0);
            sacc[nt][1] = __expf(sacc[nt][1] - mn0);
            sacc[nt][2] = __expf(sacc[nt][2] - mn1);
            sacc[nt][3] = __expf(sacc[nt][3] - mn1);
            rs0 += sacc[nt][0] + sacc[nt][1];
            rs1 += sacc[nt][2] + sacc[nt][3];
        }
        rs0 += __shfl_xor_sync(0xffffffffu, rs0, 1);
        rs0 += __shfl_xor_sync(0xffffffffu, rs0, 2);
        rs1 += __shfl_xor_sync(0xffffffffu, rs1, 1);
        rs1 += __shfl_xor_sync(0xffffffffu, rs1, 2);
        l0 = l0 * corr0 + rs0;
        l1 = l1 * corr1 + rs1;
        m0 = mn0; m1 = mn1;
        #pragma unroll
        for (int nt = 0; nt < 8; nt++) {
            oacc[nt][0] *= corr0; oacc[nt][1] *= corr0;
            oacc[nt][2] *= corr1; oacc[nt][3] *= corr1;
        }

        // store P (warp-private rows of Ps)
        #pragma unroll
        for (int nt = 0; nt < 8; nt++) {
            uint2 u0 = { f2tf32(sacc[nt][0]), f2tf32(sacc[nt][1]) };
            uint2 u1 = { f2tf32(sacc[nt][2]), f2tf32(sacc[nt][3]) };
            *(uint2*)&Ps[(wr + gr    ) * FQ + nt * 8 + 2 * tg] = u0;
            *(uint2*)&Ps[(wr + gr + 8) * FQ + nt * 8 + 2 * tg] = u1;
        }
        __syncwarp();

        // O += P @ V
        #pragma unroll
        for (int ks = 0; ks < 8; ks++) {
            int kb = ks * 8;
            unsigned pa0 = Ps[(wr + gr    ) * FQ + kb + tg    ];
            unsigned pa1 = Ps[(wr + gr + 8) * FQ + kb + tg    ];
            unsigned pa2 = Ps[(wr + gr    ) * FQ + kb + tg + 4];
            unsigned pa3 = Ps[(wr + gr + 8) * FQ + kb + tg + 4];
            #pragma unroll
            for (int nt = 0; nt < 8; nt++) {
                unsigned b0 = Vs[(kb + tg    ) * FV + nt * 8 + gr];
                unsigned b1 = Vs[(kb + tg + 4) * FV + nt * 8 + gr];
                mma8(oacc[nt], pa0, pa1, pa2, pa3, b0, b1);
            }
        }
    }

    float i0 = 1.f / l0, i1 = 1.f / l1;
    long orow0 = ((long)b * Tt + qb * 128 + wr + gr) * Cc + h * HSs;
    long orow1 = orow0 + 8L * Cc;
    #pragma unroll
    for (int nt = 0; nt < 8; nt++) {
        int c = nt * 8 + 2 * tg;
        *(float2*)(attn + orow0 + c) = make_float2(oacc[nt][0] * i0, oacc[nt][1] * i0);
        *(float2*)(attn + orow1 + c) = make_float2(oacc[nt][2] * i1, oacc[nt][3] * i1);
    }
}

// ---------------- host side ----------------
static float* symaddr(const void* sym) {
    void* p = nullptr;
    cudaGetSymbolAddress(&p, sym);
    return (float*)p;
}

static cudaStream_t make_stream() {
    cudaStream_t s;
    cudaStreamCreateWithFlags(&s, cudaStreamNonBlocking);
    return s;
}
static cudaEvent_t make_event() {
    cudaEvent_t e;
    cudaEventCreateWithFlags(&e, cudaEventDisableTiming);
    return e;
}

extern "C" void kernel_launch(void* const* d_in, const int* in_sizes, int n_in,
                              void* d_out, int out_size)
{
    const float* x      = (const float*)d_in[0];
    const float* Wq     = (const float*)d_in[1];
    const float* Wk     = (const float*)d_in[2];
    const float* Wv     = (const float*)d_in[3];
    const float* Wp     = (const float*)d_in[4];
    const float* bp     = (const float*)d_in[5];
    const float* scale1 = (const float*)d_in[6];
    const float* scale2 = (const float*)d_in[7];
    const float* W1     = (const float*)d_in[8];
    const float* b1     = (const float*)d_in[9];
    const float* W2     = (const float*)d_in[10];
    const float* b2     = (const float*)d_in[11];
    const float* Wo_in  = (const float*)d_in[12];
    const float* Wo_out = (const float*)d_in[13];
    float* out = (float*)d_out;

    float* h1   = symaddr(g_h1);
    float* qkv  = symaddr(g_qkv);
    float* attn = symaddr(g_attn);
    float* h2   = symaddr(g_h2);
    float* h3   = symaddr(g_h3);
    float* ff   = symaddr(g_ff);
    float* X0   = symaddr(g_X0);
    float* X1   = symaddr(g_X1);
    float* W2p  = symaddr(g_W2p);
    float* Wqkv = symaddr(g_Wqkv);
    float* W1p  = symaddr(g_W1p);
    float* b2f  = symaddr(g_b2f);

    // persistent side-stream + fork/join events (created once, outside capture)
    static cudaStream_t s2   = make_stream();
    static cudaEvent_t eFork = make_event();
    static cudaEvent_t eNS   = make_event();

    cudaFuncSetAttribute(flash_tc, cudaFuncAttributeMaxDynamicSharedMemorySize, FLASH_SMEM);
    cudaFuncSetAttribute(gemm_ca<false,false,false>, cudaFuncAttributeMaxDynamicSharedMemorySize, GEMM_SMEM);
    cudaFuncSetAttribute(gemm_ca<false,true,true>,   cudaFuncAttributeMaxDynamicSharedMemorySize, GEMM_SMEM);
    cudaFuncSetAttribute(gemm_ca<true,true,false>,   cudaFuncAttributeMaxDynamicSharedMemorySize, GEMM_SMEM);
    cudaFuncSetAttribute(gemm_ca<false,true,false>,  cudaFuncAttributeMaxDynamicSharedMemorySize, GEMM_SMEM);
    cudaFuncSetAttribute(gemm_ca<false,false,true>,  cudaFuncAttributeMaxDynamicSharedMemorySize, GEMM_SMEM);

    // ---- fork: Newton-Schulz on side stream (independent of the main chain) ----
    cudaEventRecord(eFork, 0);
    cudaStreamWaitEvent(s2, eFork, 0);
    ns_k<<<NS_CTAS, 256, 0, s2>>>(Wo_in, Wo_out);
    cudaEventRecord(eNS, s2);
    const float* O_in  = X0;           // result lives in g_X0 (NS_ITERS even)
    const float* O_out = X0 + MSZ;

    // ---- main chain (no NS dependency) ----
    pack_k<<<(Hh * Cc * HSs + 255) / 256, 256>>>(Wq, Wk, Wv, Wqkv);
    padW1_k<<<(Cc * PPAD + 255) / 256, 256>>>(W1, W1p);
    padW2_k<<<(PPAD * Cc + 255) / 256, 256>>>(W2, W2p);
    rmsnorm_k<<<BT / 8, 256>>>(x, scale1, h1);

    gemm_ca<false, false, false><<<dim3(C3 / 128, BT / 128), 128, GEMM_SMEM>>>(
        h1, Wqkv, nullptr, nullptr, qkv, C3, Cc, Cc, C3, C3, Cc);

    flash_tc<<<dim3(Tt / 128, Hh, Bb), 256, FLASH_SMEM>>>(qkv, attn);

    gemm_ca<false, true, true><<<dim3(Cc / 128, BT / 128), 128, GEMM_SMEM>>>(
        attn, Wp, bp, h1, h2, Cc, Cc, Cc, Cc, Cc, Cc);

    rmsnorm_k<<<BT / 8, 256>>>(h2, scale2, h3);

    // ---- join: folds need the orthogonalized matrices ----
    cudaStreamWaitEvent(0, eNS, 0);

    float* W1f = X1;                   // [Cc x PPAD] = O_in @ W1p
    float* W2f = X1 + MSZ;             // [PPAD x Cc] = W2p @ O_out + W2p
    gemm_ca<false, false, false><<<dim3(PPAD / 128, Cc / 128), 128, GEMM_SMEM>>>(
        O_in, W1p, nullptr, nullptr, W1f, PPAD, Cc, Cc, PPAD, PPAD, Cc);
    gemm_ca<false, false, true><<<dim3(Cc / 128, PPAD / 128), 128, GEMM_SMEM>>>(
        W2p, O_out, nullptr, W2p, W2f, Cc, Cc, Cc, Cc, Cc, Cc);
    b2f_k<<<(Cc + 255) / 256, 256>>>(b2, O_out, b2f);

    // ---- ff = relu(h3 @ W1f + b1)  (O_in folded; bias guarded to 307 real cols) ----
    gemm_ca<true, true, false><<<dim3(PPAD / 128, BT / 128), 128, GEMM_SMEM>>>(
        h3, W1f, b1, nullptr, ff, PPAD, Cc, Cc, PPAD, Pp, Cc);

    // ---- out = ff @ W2f + b2f  (W2, O_out, +identity residual all folded) ----
    gemm_ca<false, true, false><<<dim3(Cc / 128, BT / 128), 128, GEMM_SMEM>>>(
        ff, W2f, b2f, nullptr, out, Cc, PPAD, PPAD, Cc, Cc, PPAD);

    (void)in_sizes; (void)n_in; (void)out_size;
}